// round 8
// baseline (speedup 1.0000x reference)
#include <cuda_runtime.h>
#include <cuda_bf16.h>
#include <cuda_fp16.h>
#include <stdint.h>
#include <math.h>

// Problem constants (fixed by the dataset)
#define NN 100000
#define EE 3200000
#define FIN 128
#define HH  256
#define GG  64
#define HO  128   // H/2

typedef unsigned long long u64;

// ---------------- per-pass scratch (static device globals) --------------------
#define NH ((size_t)NN * HH)
__device__ __align__(16) __half g_hh[3][NH];                  // fp16 h (gather source)
__device__ __align__(16) __half g_xh[3][(size_t)NN * FIN];    // fp16 x
__device__ __align__(16) float g_p0[3][NH];
__device__ __align__(16) float g_p1[3][NH];
__device__ float g_dinv [3][NN];
__device__ float g_dinv2[3][NN];
__device__ int   g_deg  [3][NN];
__device__ __align__(16) float g_psum[3][GG * HH];
__device__ int   g_pcnt[3][GG];
__device__ int   g_rowptr[3][NN + 1];
__device__ int   g_off[3][NN];
__device__ int   g_bsum[3][128];
__device__ int   g_bsum2[3][128];
__device__ __align__(8) int2 g_epack[3][EE];   // (src, coef-as-int)

// ---------------- helpers ----------------------------------------------------
__device__ __forceinline__ void red_add_v4(float4* addr, float4 v) {
    asm volatile("red.global.add.v4.f32 [%0], {%1,%2,%3,%4};"
                 :: "l"(addr), "f"(v.x), "f"(v.y), "f"(v.z), "f"(v.w)
                 : "memory");
}
__device__ __forceinline__ u64 dup2(float a) {
    u64 r; asm("mov.b64 %0, {%1, %1};" : "=l"(r) : "f"(a)); return r;
}
__device__ __forceinline__ void fma2(u64& acc, u64 a, u64 b) {
    asm("fma.rn.f32x2 %0, %1, %2, %0;" : "+l"(acc) : "l"(a), "l"(b));
}
__device__ __forceinline__ float2 unp2(u64 v) {
    float2 f; asm("mov.b64 {%0, %1}, %2;" : "=f"(f.x), "=f"(f.y) : "l"(v)); return f;
}

// ---------------- per-pass setup ---------------------------------------------
__global__ void zero_kernel(int p) {
    int i = blockIdx.x * blockDim.x + threadIdx.x;
    if (i < NN)      { g_deg[p][i] = 0; g_off[p][i] = 0; }
    if (i < GG * HH) g_psum[p][i] = 0.f;
    if (i < GG)      g_pcnt[p][i] = 0;
}

__global__ void deg_kernel(const int* __restrict__ dst, int p) {
    int e = blockIdx.x * blockDim.x + threadIdx.x;
    if (e < EE) atomicAdd(&g_deg[p][dst[e]], 1);
}

__global__ void dinv_kernel(int p) {
    int i = blockIdx.x * blockDim.x + threadIdx.x;
    if (i < NN) {
        float d = (float)g_deg[p][i] + 1.0f;
        g_dinv[p][i]  = rsqrtf(d);
        g_dinv2[p][i] = 1.0f / d;
    }
}

// x fp32 -> fp16
__global__ void xcvt_kernel(const float* __restrict__ x, __half* __restrict__ xh) {
    size_t i = ((size_t)blockIdx.x * blockDim.x + threadIdx.x) * 4;
    if (i >= (size_t)NN * FIN) return;
    float4 v = *reinterpret_cast<const float4*>(x + i);
    __half2 a = __float22half2_rn(make_float2(v.x, v.y));
    __half2 b = __float22half2_rn(make_float2(v.z, v.w));
    uint2 s;
    s.x = *reinterpret_cast<uint32_t*>(&a);
    s.y = *reinterpret_cast<uint32_t*>(&b);
    *reinterpret_cast<uint2*>(xh + i) = s;
}

// ---------------- exclusive scan of deg -> rowptr ------------------------------
__global__ void scan1_kernel(int p) {
    __shared__ int s[1024];
    int t = threadIdx.x;
    int i = blockIdx.x * 1024 + t;
    int v = (i < NN) ? g_deg[p][i] : 0;
    int x = v;
    s[t] = x;
    __syncthreads();
#pragma unroll
    for (int off = 1; off < 1024; off <<= 1) {
        int y = (t >= off) ? s[t - off] : 0;
        __syncthreads();
        x += y;
        s[t] = x;
        __syncthreads();
    }
    if (i < NN) g_rowptr[p][i] = x - v;
    if (t == 1023) g_bsum[p][blockIdx.x] = x;
}

__global__ void scan2_kernel(int p) {
    __shared__ int s[128];
    int t = threadIdx.x;
    const int NB = (NN + 1023) >> 10;
    int v = (t < NB) ? g_bsum[p][t] : 0;
    int x = v;
    s[t] = x;
    __syncthreads();
#pragma unroll
    for (int off = 1; off < 128; off <<= 1) {
        int y = (t >= off) ? s[t - off] : 0;
        __syncthreads();
        x += y;
        s[t] = x;
        __syncthreads();
    }
    g_bsum2[p][t] = x - v;
}

__global__ void scan3_kernel(int p) {
    int i = blockIdx.x * blockDim.x + threadIdx.x;
    if (i < NN) g_rowptr[p][i] += g_bsum2[p][i >> 10];
    if (i == 0) g_rowptr[p][NN] = EE;
}

__global__ void csr_kernel(const int* __restrict__ src, const int* __restrict__ dst, int p) {
    int e = blockIdx.x * blockDim.x + threadIdx.x;
    if (e >= EE) return;
    int s = src[e], d = dst[e];
    float coef = g_dinv[p][s] * g_dinv[p][d];
    int pos = g_rowptr[p][d] + atomicAdd(&g_off[p][d], 1);
    g_epack[p][pos] = make_int2(s, __float_as_int(coef));
}

__global__ void pcnt_kernel(const int* __restrict__ batch, int p) {
    int i = blockIdx.x * blockDim.x + threadIdx.x;
    if (i < NN) atomicAdd(&g_pcnt[p][batch[i]], 1);
}

// ---------------- layer-0 input aggregation: aggx = Â x  (fp16 gather) ---------
// One warp per node; lane handles 4 cols (uint2 = 4 halves per edge).
__global__ void __launch_bounds__(256)
pullx_kernel(const __half* __restrict__ xh, float* __restrict__ aggx, int p)
{
    int n = (int)((blockIdx.x * (unsigned)blockDim.x + threadIdx.x) >> 5);
    int lane = threadIdx.x & 31;
    if (n >= NN) return;
    int c = lane * 4;

    float d2 = g_dinv2[p][n];
    uint2 sv = *reinterpret_cast<const uint2*>(xh + (size_t)n * FIN + c);
    float2 s0 = __half22float2(*reinterpret_cast<__half2*>(&sv.x));
    float2 s1 = __half22float2(*reinterpret_cast<__half2*>(&sv.y));
    float4 acc = make_float4(s0.x * d2, s0.y * d2, s1.x * d2, s1.y * d2);

    int e = g_rowptr[p][n];
    int end = g_rowptr[p][n + 1];
    const int2* ep = g_epack[p];

    for (; e + 1 < end; e += 2) {
        int2 p0 = ep[e + 0];
        int2 p1 = ep[e + 1];
        uint2 v0 = *reinterpret_cast<const uint2*>(xh + (size_t)p0.x * FIN + c);
        uint2 v1 = *reinterpret_cast<const uint2*>(xh + (size_t)p1.x * FIN + c);
        float c0 = __int_as_float(p0.y), c1 = __int_as_float(p1.y);
        float2 a0 = __half22float2(*reinterpret_cast<__half2*>(&v0.x));
        float2 a1 = __half22float2(*reinterpret_cast<__half2*>(&v0.y));
        float2 b0 = __half22float2(*reinterpret_cast<__half2*>(&v1.x));
        float2 b1 = __half22float2(*reinterpret_cast<__half2*>(&v1.y));
        acc.x = fmaf(c0, a0.x, acc.x); acc.y = fmaf(c0, a0.y, acc.y);
        acc.z = fmaf(c0, a1.x, acc.z); acc.w = fmaf(c0, a1.y, acc.w);
        acc.x = fmaf(c1, b0.x, acc.x); acc.y = fmaf(c1, b0.y, acc.y);
        acc.z = fmaf(c1, b1.x, acc.z); acc.w = fmaf(c1, b1.y, acc.w);
    }
    for (; e < end; e++) {
        int2 pe = ep[e];
        uint2 v = *reinterpret_cast<const uint2*>(xh + (size_t)pe.x * FIN + c);
        float cf = __int_as_float(pe.y);
        float2 a0 = __half22float2(*reinterpret_cast<__half2*>(&v.x));
        float2 a1 = __half22float2(*reinterpret_cast<__half2*>(&v.y));
        acc.x = fmaf(cf, a0.x, acc.x); acc.y = fmaf(cf, a0.y, acc.y);
        acc.z = fmaf(cf, a1.x, acc.z); acc.w = fmaf(cf, a1.y, acc.w);
    }

    *reinterpret_cast<float4*>(aggx + (size_t)n * FIN + c) = acc;
}

// ---------------- GEMM: out = act(A) @ W (+bias | fp16)  (FFMA2 128x128) ------
template <int K, bool RELU, bool BIAS, bool HALFOUT>
__global__ void __launch_bounds__(256, 2)
gemm2_kernel(const float* __restrict__ A, const float* __restrict__ W,
             const float* __restrict__ bias, float* __restrict__ HoutF,
             __half* __restrict__ HoutH)
{
    __shared__ float As[16][132];
    __shared__ float Bs[16][128];

    const int t  = threadIdx.x;
    const int tx = t & 15;
    const int ty = t >> 4;
    const int rowBase = blockIdx.x * 128;
    const int colBase = blockIdx.y * 128;

    const int arow = t >> 2;
    const int akg  = (t & 3) * 4;
    const int brow = t >> 5;
    const int bcol = (t & 31) * 4;

    const int r0 = rowBase + arow;
    const int r1 = r0 + 64;

    u64 acc[8][4];
#pragma unroll
    for (int i = 0; i < 8; i++)
#pragma unroll
        for (int j = 0; j < 4; j++) acc[i][j] = 0ull;

    float4 pa0, pa1, pb0, pb1;
    {
        pa0 = make_float4(0.f, 0.f, 0.f, 0.f); pa1 = pa0;
        if (r0 < NN) pa0 = *reinterpret_cast<const float4*>(A + (size_t)r0 * K + akg);
        if (r1 < NN) pa1 = *reinterpret_cast<const float4*>(A + (size_t)r1 * K + akg);
        pb0 = *reinterpret_cast<const float4*>(W + (size_t)brow * HH + colBase + bcol);
        pb1 = *reinterpret_cast<const float4*>(W + (size_t)(8 + brow) * HH + colBase + bcol);
    }

    for (int k0 = 0; k0 < K; k0 += 16) {
        float4 a0 = pa0, a1 = pa1, b0 = pb0, b1 = pb1;
        if (RELU) {
            a0.x = fmaxf(a0.x, 0.f); a0.y = fmaxf(a0.y, 0.f);
            a0.z = fmaxf(a0.z, 0.f); a0.w = fmaxf(a0.w, 0.f);
            a1.x = fmaxf(a1.x, 0.f); a1.y = fmaxf(a1.y, 0.f);
            a1.z = fmaxf(a1.z, 0.f); a1.w = fmaxf(a1.w, 0.f);
        }
        As[akg + 0][arow] = a0.x; As[akg + 1][arow] = a0.y;
        As[akg + 2][arow] = a0.z; As[akg + 3][arow] = a0.w;
        As[akg + 0][64 + arow] = a1.x; As[akg + 1][64 + arow] = a1.y;
        As[akg + 2][64 + arow] = a1.z; As[akg + 3][64 + arow] = a1.w;
        *reinterpret_cast<float4*>(&Bs[brow][bcol])     = b0;
        *reinterpret_cast<float4*>(&Bs[brow + 8][bcol]) = b1;
        __syncthreads();

        if (k0 + 16 < K) {
            int kn = k0 + 16;
            pa0 = make_float4(0.f, 0.f, 0.f, 0.f); pa1 = pa0;
            if (r0 < NN) pa0 = *reinterpret_cast<const float4*>(A + (size_t)r0 * K + kn + akg);
            if (r1 < NN) pa1 = *reinterpret_cast<const float4*>(A + (size_t)r1 * K + kn + akg);
            pb0 = *reinterpret_cast<const float4*>(W + (size_t)(kn + brow) * HH + colBase + bcol);
            pb1 = *reinterpret_cast<const float4*>(W + (size_t)(kn + 8 + brow) * HH + colBase + bcol);
        }

#pragma unroll
        for (int kk = 0; kk < 16; kk++) {
            float4 av0 = *reinterpret_cast<const float4*>(&As[kk][ty * 4]);
            float4 av1 = *reinterpret_cast<const float4*>(&As[kk][64 + ty * 4]);
            ulonglong2 bv0 = *reinterpret_cast<const ulonglong2*>(&Bs[kk][tx * 4]);
            ulonglong2 bv1 = *reinterpret_cast<const ulonglong2*>(&Bs[kk][64 + tx * 4]);
            u64 aa;
            aa = dup2(av0.x);
            fma2(acc[0][0], aa, bv0.x); fma2(acc[0][1], aa, bv0.y);
            fma2(acc[0][2], aa, bv1.x); fma2(acc[0][3], aa, bv1.y);
            aa = dup2(av0.y);
            fma2(acc[1][0], aa, bv0.x); fma2(acc[1][1], aa, bv0.y);
            fma2(acc[1][2], aa, bv1.x); fma2(acc[1][3], aa, bv1.y);
            aa = dup2(av0.z);
            fma2(acc[2][0], aa, bv0.x); fma2(acc[2][1], aa, bv0.y);
            fma2(acc[2][2], aa, bv1.x); fma2(acc[2][3], aa, bv1.y);
            aa = dup2(av0.w);
            fma2(acc[3][0], aa, bv0.x); fma2(acc[3][1], aa, bv0.y);
            fma2(acc[3][2], aa, bv1.x); fma2(acc[3][3], aa, bv1.y);
            aa = dup2(av1.x);
            fma2(acc[4][0], aa, bv0.x); fma2(acc[4][1], aa, bv0.y);
            fma2(acc[4][2], aa, bv1.x); fma2(acc[4][3], aa, bv1.y);
            aa = dup2(av1.y);
            fma2(acc[5][0], aa, bv0.x); fma2(acc[5][1], aa, bv0.y);
            fma2(acc[5][2], aa, bv1.x); fma2(acc[5][3], aa, bv1.y);
            aa = dup2(av1.z);
            fma2(acc[6][0], aa, bv0.x); fma2(acc[6][1], aa, bv0.y);
            fma2(acc[6][2], aa, bv1.x); fma2(acc[6][3], aa, bv1.y);
            aa = dup2(av1.w);
            fma2(acc[7][0], aa, bv0.x); fma2(acc[7][1], aa, bv0.y);
            fma2(acc[7][2], aa, bv1.x); fma2(acc[7][3], aa, bv1.y);
        }
        __syncthreads();
    }

    float4 bias0 = make_float4(0.f, 0.f, 0.f, 0.f), bias1 = bias0;
    if (BIAS) {
        bias0 = *reinterpret_cast<const float4*>(bias + colBase + tx * 4);
        bias1 = *reinterpret_cast<const float4*>(bias + colBase + 64 + tx * 4);
    }
#pragma unroll
    for (int i = 0; i < 8; i++) {
        int r = rowBase + ((i < 4) ? (ty * 4 + i) : (64 + ty * 4 + (i - 4)));
        if (r < NN) {
            float2 c0 = unp2(acc[i][0]), c1 = unp2(acc[i][1]);
            float2 c2 = unp2(acc[i][2]), c3 = unp2(acc[i][3]);
            float4 o0 = make_float4(c0.x, c0.y, c1.x, c1.y);
            float4 o1 = make_float4(c2.x, c2.y, c3.x, c3.y);
            if (BIAS) {
                o0.x += bias0.x; o0.y += bias0.y; o0.z += bias0.z; o0.w += bias0.w;
                o1.x += bias1.x; o1.y += bias1.y; o1.z += bias1.z; o1.w += bias1.w;
            }
            if (HALFOUT) {
                __half2 h0 = __float22half2_rn(make_float2(o0.x, o0.y));
                __half2 h1 = __float22half2_rn(make_float2(o0.z, o0.w));
                __half2 h2 = __float22half2_rn(make_float2(o1.x, o1.y));
                __half2 h3 = __float22half2_rn(make_float2(o1.z, o1.w));
                uint2 s0, s1;
                s0.x = *reinterpret_cast<uint32_t*>(&h0);
                s0.y = *reinterpret_cast<uint32_t*>(&h1);
                s1.x = *reinterpret_cast<uint32_t*>(&h2);
                s1.y = *reinterpret_cast<uint32_t*>(&h3);
                *reinterpret_cast<uint2*>(HoutH + (size_t)r * HH + colBase + tx * 4) = s0;
                *reinterpret_cast<uint2*>(HoutH + (size_t)r * HH + colBase + 64 + tx * 4) = s1;
            } else {
                *reinterpret_cast<float4*>(HoutF + (size_t)r * HH + colBase + tx * 4) = o0;
                *reinterpret_cast<float4*>(HoutF + (size_t)r * HH + colBase + 64 + tx * 4) = o1;
            }
        }
    }
}

// ---------------- pull aggregation (fp16 gather, all 256 cols per warp) --------
// doPool==1: skip node-output store (only the pooled sum is consumed downstream).
__global__ void __launch_bounds__(256)
pull_kernel(const float* __restrict__ bias, const __half* __restrict__ h,
            float* __restrict__ out, const int* __restrict__ batch,
            int doPool, int p)
{
    int n = (int)((blockIdx.x * (unsigned)blockDim.x + threadIdx.x) >> 5);
    int lane = threadIdx.x & 31;
    if (n >= NN) return;
    int c = lane * 8;  // 8 cols per lane (uint4 = 8 halves)

    float d2 = g_dinv2[p][n];
    float4 ba = *reinterpret_cast<const float4*>(bias + c);
    float4 bb = *reinterpret_cast<const float4*>(bias + c + 4);
    uint4 sv = *reinterpret_cast<const uint4*>(h + (size_t)n * HH + c);
    float2 s0 = __half22float2(*reinterpret_cast<__half2*>(&sv.x));
    float2 s1 = __half22float2(*reinterpret_cast<__half2*>(&sv.y));
    float2 s2 = __half22float2(*reinterpret_cast<__half2*>(&sv.z));
    float2 s3 = __half22float2(*reinterpret_cast<__half2*>(&sv.w));
    float4 accA = make_float4(fmaf(s0.x, d2, ba.x), fmaf(s0.y, d2, ba.y),
                              fmaf(s1.x, d2, ba.z), fmaf(s1.y, d2, ba.w));
    float4 accB = make_float4(fmaf(s2.x, d2, bb.x), fmaf(s2.y, d2, bb.y),
                              fmaf(s3.x, d2, bb.z), fmaf(s3.y, d2, bb.w));

    int e = g_rowptr[p][n];
    int end = g_rowptr[p][n + 1];
    const int2* ep = g_epack[p];

    for (; e + 1 < end; e += 2) {
        int2 p0 = ep[e + 0];
        int2 p1 = ep[e + 1];
        uint4 v0 = *reinterpret_cast<const uint4*>(h + (size_t)p0.x * HH + c);
        uint4 v1 = *reinterpret_cast<const uint4*>(h + (size_t)p1.x * HH + c);
        float c0 = __int_as_float(p0.y), c1 = __int_as_float(p1.y);
        {
            float2 a0 = __half22float2(*reinterpret_cast<__half2*>(&v0.x));
            float2 a1 = __half22float2(*reinterpret_cast<__half2*>(&v0.y));
            float2 a2 = __half22float2(*reinterpret_cast<__half2*>(&v0.z));
            float2 a3 = __half22float2(*reinterpret_cast<__half2*>(&v0.w));
            accA.x = fmaf(c0, a0.x, accA.x); accA.y = fmaf(c0, a0.y, accA.y);
            accA.z = fmaf(c0, a1.x, accA.z); accA.w = fmaf(c0, a1.y, accA.w);
            accB.x = fmaf(c0, a2.x, accB.x); accB.y = fmaf(c0, a2.y, accB.y);
            accB.z = fmaf(c0, a3.x, accB.z); accB.w = fmaf(c0, a3.y, accB.w);
        }
        {
            float2 a0 = __half22float2(*reinterpret_cast<__half2*>(&v1.x));
            float2 a1 = __half22float2(*reinterpret_cast<__half2*>(&v1.y));
            float2 a2 = __half22float2(*reinterpret_cast<__half2*>(&v1.z));
            float2 a3 = __half22float2(*reinterpret_cast<__half2*>(&v1.w));
            accA.x = fmaf(c1, a0.x, accA.x); accA.y = fmaf(c1, a0.y, accA.y);
            accA.z = fmaf(c1, a1.x, accA.z); accA.w = fmaf(c1, a1.y, accA.w);
            accB.x = fmaf(c1, a2.x, accB.x); accB.y = fmaf(c1, a2.y, accB.y);
            accB.z = fmaf(c1, a3.x, accB.z); accB.w = fmaf(c1, a3.y, accB.w);
        }
    }
    for (; e < end; e++) {
        int2 pe = ep[e];
        uint4 v = *reinterpret_cast<const uint4*>(h + (size_t)pe.x * HH + c);
        float cf = __int_as_float(pe.y);
        float2 a0 = __half22float2(*reinterpret_cast<__half2*>(&v.x));
        float2 a1 = __half22float2(*reinterpret_cast<__half2*>(&v.y));
        float2 a2 = __half22float2(*reinterpret_cast<__half2*>(&v.z));
        float2 a3 = __half22float2(*reinterpret_cast<__half2*>(&v.w));
        accA.x = fmaf(cf, a0.x, accA.x); accA.y = fmaf(cf, a0.y, accA.y);
        accA.z = fmaf(cf, a1.x, accA.z); accA.w = fmaf(cf, a1.y, accA.w);
        accB.x = fmaf(cf, a2.x, accB.x); accB.y = fmaf(cf, a2.y, accB.y);
        accB.z = fmaf(cf, a3.x, accB.z); accB.w = fmaf(cf, a3.y, accB.w);
    }

    if (!doPool) {
        *reinterpret_cast<float4*>(out + (size_t)n * HH + c)     = accA;
        *reinterpret_cast<float4*>(out + (size_t)n * HH + c + 4) = accB;
    } else {
        int g = __ldg(&batch[n]);
        red_add_v4(reinterpret_cast<float4*>(g_psum[p] + g * HH + c), accA);
        red_add_v4(reinterpret_cast<float4*>(g_psum[p] + g * HH + c + 4), accB);
    }
}

// ---------------- z = mean @ lin0_W + lin0_b -----------------------------------
__global__ void __launch_bounds__(128)
z_kernel(const float* __restrict__ lin0W, const float* __restrict__ lin0b,
         float* __restrict__ outz, int p)
{
    __shared__ float mean[HH];
    int g = blockIdx.x;
    int t = threadIdx.x;
    float c = fmaxf((float)g_pcnt[p][g], 1.0f);
    mean[t]       = g_psum[p][g * HH + t] / c;
    mean[t + 128] = g_psum[p][g * HH + t + 128] / c;
    __syncthreads();
    float acc = lin0b[t];
#pragma unroll 8
    for (int k = 0; k < HH; k++)
        acc = fmaf(mean[k], __ldg(&lin0W[(size_t)k * HO + t]), acc);
    outz[g * HO + t] = acc;
}

// ---------------- triplet head ------------------------------------------------
__global__ void final_kernel(const float* __restrict__ linW,
                             const float* __restrict__ linb,
                             float* __restrict__ out)
{
    __shared__ int s1, s2;
    int g = threadIdx.x;
    if (g == 0) { s1 = 0; s2 = 0; }
    __syncthreads();

    const float* z0 = out;
    const float* z1 = out + GG * HO;
    const float* z2 = out + 2 * GG * HO;
    const float EPS = 1e-6f;

    float dp = 0.f, dn = 0.f;
    float y1 = linb[0], y2 = linb[0];
#pragma unroll 4
    for (int j = 0; j < HO; j++) {
        float a = z0[g * HO + j];
        float b = z1[g * HO + j];
        float c = z2[g * HO + j];
        float e1 = a - b + EPS; dp = fmaf(e1, e1, dp);
        float e2 = a - c + EPS; dn = fmaf(e2, e2, dn);
        float wa = linW[j], wb = linW[HO + j];
        y1 = fmaf(a, wa, fmaf(b, wb, y1));
        y2 = fmaf(a, wa, fmaf(c, wb, y2));
    }
    dp = sqrtf(dp); dn = sqrtf(dn);
    float sp = 1.0f / (1.0f + expf(-y1));
    float sn = 1.0f / (1.0f + expf(-y2));

    const int base = 3 * GG * HO;
    out[base + 1 + g] = sp;
    out[base + 1 + GG + g] = sn;
    if (dn - dp > 0.f) atomicAdd(&s1, 1);
    if (sp - sn > 0.f) atomicAdd(&s2, 1);
    __syncthreads();
    if (g == 0) {
        out[base] = (float)s1;
        out[base + 1 + 2 * GG] = (float)s2;
    }
}

// ---------------- host orchestration ------------------------------------------
extern "C" void kernel_launch(void* const* d_in, const int* in_sizes, int n_in,
                              void* d_out, int out_size)
{
    const float* x[3]     = { (const float*)d_in[0], (const float*)d_in[1], (const float*)d_in[2] };
    const int*   ei[3]    = { (const int*)d_in[3], (const int*)d_in[4], (const int*)d_in[5] };
    const int*   batch[3] = { (const int*)d_in[6], (const int*)d_in[7], (const int*)d_in[8] };
    const float* W0 = (const float*)d_in[9];
    const float* b0 = (const float*)d_in[10];
    const float* W1 = (const float*)d_in[11];
    const float* b1 = (const float*)d_in[12];
    const float* W2 = (const float*)d_in[13];
    const float* b2 = (const float*)d_in[14];
    const float* lin0W = (const float*)d_in[15];
    const float* lin0b = (const float*)d_in[16];
    const float* linW  = (const float*)d_in[17];
    const float* linb  = (const float*)d_in[18];
    float* out = (float*)d_out;

    static cudaStream_t st[3];
    static cudaEvent_t evRoot, evDone[3];
    static bool inited = false;
    if (!inited) {
        for (int i = 0; i < 3; i++) cudaStreamCreateWithFlags(&st[i], cudaStreamNonBlocking);
        cudaEventCreateWithFlags(&evRoot, cudaEventDisableTiming);
        for (int i = 0; i < 3; i++) cudaEventCreateWithFlags(&evDone[i], cudaEventDisableTiming);
        inited = true;
    }

    float *p0ptr[3], *p1ptr[3];
    __half *hhptr[3], *xhptr[3];
    {
        float* base;
        cudaGetSymbolAddress((void**)&base, g_p0);
        for (int i = 0; i < 3; i++) p0ptr[i] = base + (size_t)i * NH;
        cudaGetSymbolAddress((void**)&base, g_p1);
        for (int i = 0; i < 3; i++) p1ptr[i] = base + (size_t)i * NH;
        __half* hb;
        cudaGetSymbolAddress((void**)&hb, g_hh);
        for (int i = 0; i < 3; i++) hhptr[i] = hb + (size_t)i * NH;
        cudaGetSymbolAddress((void**)&hb, g_xh);
        for (int i = 0; i < 3; i++) xhptr[i] = hb + (size_t)i * NN * FIN;
    }

    dim3 gemmGrid((NN + 127) / 128, HH / 128);
    int  warpBlocks = (int)(((long long)NN * 32 + 255) / 256);
    const int NB = (NN + 1023) / 1024;
    int  xcvtBlocks = (int)(((size_t)NN * FIN / 4 + 255) / 256);

    cudaEventRecord(evRoot, 0);

    for (int p = 0; p < 3; p++) {
        cudaStream_t s = st[p];
        cudaStreamWaitEvent(s, evRoot, 0);

        const int* srcp = ei[p];
        const int* dstp = ei[p] + EE;

        // ---- per-pass graph prep + x conversion ----
        zero_kernel<<<(NN + 255) / 256, 256, 0, s>>>(p);
        xcvt_kernel<<<xcvtBlocks, 256, 0, s>>>(x[p], xhptr[p]);
        deg_kernel<<<(EE + 255) / 256, 256, 0, s>>>(dstp, p);
        dinv_kernel<<<(NN + 255) / 256, 256, 0, s>>>(p);
        scan1_kernel<<<NB, 1024, 0, s>>>(p);
        scan2_kernel<<<1, 128, 0, s>>>(p);
        scan3_kernel<<<(NN + 255) / 256, 256, 0, s>>>(p);
        csr_kernel<<<(EE + 255) / 256, 256, 0, s>>>(srcp, dstp, p);
        pcnt_kernel<<<(NN + 255) / 256, 256, 0, s>>>(batch[p], p);

        // ---- layer 0 (aggregate-first): aggx = Â x -> p1 ; p0 = aggx@W0 + b0
        pullx_kernel<<<warpBlocks, 256, 0, s>>>(xhptr[p], p1ptr[p], p);
        gemm2_kernel<FIN, false, true, false><<<gemmGrid, 256, 0, s>>>(
            p1ptr[p], W0, b0, p0ptr[p], nullptr);

        // ---- layer 1: hh = relu(p0)@W1 (fp16) ; pull+b1 -> p1
        gemm2_kernel<HH, true, false, true><<<gemmGrid, 256, 0, s>>>(
            p0ptr[p], W1, nullptr, nullptr, hhptr[p]);
        pull_kernel<<<warpBlocks, 256, 0, s>>>(b1, hhptr[p], p1ptr[p], nullptr, 0, p);

        // ---- layer 2: hh = relu(p1)@W2 (fp16) ; pull+b2 -> pooled only
        gemm2_kernel<HH, true, false, true><<<gemmGrid, 256, 0, s>>>(
            p1ptr[p], W2, nullptr, nullptr, hhptr[p]);
        pull_kernel<<<warpBlocks, 256, 0, s>>>(b2, hhptr[p], nullptr, batch[p], 1, p);

        // ---- z_p = mean @ lin0_W + lin0_b
        z_kernel<<<GG, 128, 0, s>>>(lin0W, lin0b, out + (size_t)p * GG * HO, p);

        cudaEventRecord(evDone[p], s);
    }

    for (int p = 0; p < 3; p++) cudaStreamWaitEvent(0, evDone[p], 0);

    final_kernel<<<1, GG>>>(linW, linb, out);
}

// round 9
// speedup vs baseline: 1.0848x; 1.0848x over previous
#include <cuda_runtime.h>
#include <cuda_bf16.h>
#include <cuda_fp16.h>
#include <stdint.h>
#include <math.h>

// Problem constants (fixed by the dataset)
#define NN 100000
#define EE 3200000
#define FIN 128
#define HH  256
#define GG  64
#define HO  128   // H/2

typedef unsigned long long u64;

// ---------------- per-pass scratch (static device globals) --------------------
#define NH ((size_t)NN * HH)
__device__ __align__(16) __half g_hh[3][NH];                  // fp16 h (gather source)
__device__ __align__(16) __half g_xh[3][(size_t)NN * FIN];    // fp16 x
__device__ __align__(16) float g_p0[3][NH];
__device__ __align__(16) float g_p1[3][NH];
__device__ float g_dinv [3][NN];
__device__ float g_dinv2[3][NN];
__device__ int   g_deg  [3][NN];
__device__ __align__(16) float g_psum[3][GG * HH];
__device__ int   g_pcnt[3][GG];
__device__ int   g_rowptr[3][NN + 1];
__device__ int   g_off[3][NN];
__device__ int   g_bsum[3][128];
__device__ int   g_bsum2[3][128];
__device__ __align__(16) int2 g_epack[3][EE];   // (src, coef-as-int)

// ---------------- helpers ----------------------------------------------------
__device__ __forceinline__ void red_add_v4(float4* addr, float4 v) {
    asm volatile("red.global.add.v4.f32 [%0], {%1,%2,%3,%4};"
                 :: "l"(addr), "f"(v.x), "f"(v.y), "f"(v.z), "f"(v.w)
                 : "memory");
}
__device__ __forceinline__ u64 dup2(float a) {
    u64 r; asm("mov.b64 %0, {%1, %1};" : "=l"(r) : "f"(a)); return r;
}
__device__ __forceinline__ void fma2(u64& acc, u64 a, u64 b) {
    asm("fma.rn.f32x2 %0, %1, %2, %0;" : "+l"(acc) : "l"(a), "l"(b));
}
__device__ __forceinline__ float2 unp2(u64 v) {
    float2 f; asm("mov.b64 {%0, %1}, %2;" : "=f"(f.x), "=f"(f.y) : "l"(v)); return f;
}
__device__ __forceinline__ void hacc4(float4& a0, float4& a1, float cf, const uint4& v) {
    float2 x0 = __half22float2(*reinterpret_cast<const __half2*>(&v.x));
    float2 x1 = __half22float2(*reinterpret_cast<const __half2*>(&v.y));
    float2 x2 = __half22float2(*reinterpret_cast<const __half2*>(&v.z));
    float2 x3 = __half22float2(*reinterpret_cast<const __half2*>(&v.w));
    a0.x = fmaf(cf, x0.x, a0.x); a0.y = fmaf(cf, x0.y, a0.y);
    a0.z = fmaf(cf, x1.x, a0.z); a0.w = fmaf(cf, x1.y, a0.w);
    a1.x = fmaf(cf, x2.x, a1.x); a1.y = fmaf(cf, x2.y, a1.y);
    a1.z = fmaf(cf, x3.x, a1.z); a1.w = fmaf(cf, x3.y, a1.w);
}
__device__ __forceinline__ void hacc2(float4& a, float cf, const uint2& v) {
    float2 x0 = __half22float2(*reinterpret_cast<const __half2*>(&v.x));
    float2 x1 = __half22float2(*reinterpret_cast<const __half2*>(&v.y));
    a.x = fmaf(cf, x0.x, a.x); a.y = fmaf(cf, x0.y, a.y);
    a.z = fmaf(cf, x1.x, a.z); a.w = fmaf(cf, x1.y, a.w);
}

// ---------------- per-pass setup ---------------------------------------------
__global__ void zero_kernel(int p) {
    int i = blockIdx.x * blockDim.x + threadIdx.x;
    if (i < NN)      { g_deg[p][i] = 0; g_off[p][i] = 0; }
    if (i < GG * HH) g_psum[p][i] = 0.f;
    if (i < GG)      g_pcnt[p][i] = 0;
}

__global__ void deg_kernel(const int* __restrict__ dst, int p) {
    int e = blockIdx.x * blockDim.x + threadIdx.x;
    if (e < EE) atomicAdd(&g_deg[p][dst[e]], 1);
}

__global__ void dinv_kernel(int p) {
    int i = blockIdx.x * blockDim.x + threadIdx.x;
    if (i < NN) {
        float d = (float)g_deg[p][i] + 1.0f;
        g_dinv[p][i]  = rsqrtf(d);
        g_dinv2[p][i] = 1.0f / d;
    }
}

// x fp32 -> fp16
__global__ void xcvt_kernel(const float* __restrict__ x, __half* __restrict__ xh) {
    size_t i = ((size_t)blockIdx.x * blockDim.x + threadIdx.x) * 4;
    if (i >= (size_t)NN * FIN) return;
    float4 v = *reinterpret_cast<const float4*>(x + i);
    __half2 a = __float22half2_rn(make_float2(v.x, v.y));
    __half2 b = __float22half2_rn(make_float2(v.z, v.w));
    uint2 s;
    s.x = *reinterpret_cast<uint32_t*>(&a);
    s.y = *reinterpret_cast<uint32_t*>(&b);
    *reinterpret_cast<uint2*>(xh + i) = s;
}

// ---------------- exclusive scan of deg -> rowptr ------------------------------
__global__ void scan1_kernel(int p) {
    __shared__ int s[1024];
    int t = threadIdx.x;
    int i = blockIdx.x * 1024 + t;
    int v = (i < NN) ? g_deg[p][i] : 0;
    int x = v;
    s[t] = x;
    __syncthreads();
#pragma unroll
    for (int off = 1; off < 1024; off <<= 1) {
        int y = (t >= off) ? s[t - off] : 0;
        __syncthreads();
        x += y;
        s[t] = x;
        __syncthreads();
    }
    if (i < NN) g_rowptr[p][i] = x - v;
    if (t == 1023) g_bsum[p][blockIdx.x] = x;
}

__global__ void scan2_kernel(int p) {
    __shared__ int s[128];
    int t = threadIdx.x;
    const int NB = (NN + 1023) >> 10;
    int v = (t < NB) ? g_bsum[p][t] : 0;
    int x = v;
    s[t] = x;
    __syncthreads();
#pragma unroll
    for (int off = 1; off < 128; off <<= 1) {
        int y = (t >= off) ? s[t - off] : 0;
        __syncthreads();
        x += y;
        s[t] = x;
        __syncthreads();
    }
    g_bsum2[p][t] = x - v;
}

__global__ void scan3_kernel(int p) {
    int i = blockIdx.x * blockDim.x + threadIdx.x;
    if (i < NN) g_rowptr[p][i] += g_bsum2[p][i >> 10];
    if (i == 0) g_rowptr[p][NN] = EE;
}

__global__ void csr_kernel(const int* __restrict__ src, const int* __restrict__ dst, int p) {
    int e = blockIdx.x * blockDim.x + threadIdx.x;
    if (e >= EE) return;
    int s = src[e], d = dst[e];
    float coef = g_dinv[p][s] * g_dinv[p][d];
    int pos = g_rowptr[p][d] + atomicAdd(&g_off[p][d], 1);
    g_epack[p][pos] = make_int2(s, __float_as_int(coef));
}

__global__ void pcnt_kernel(const int* __restrict__ batch, int p) {
    int i = blockIdx.x * blockDim.x + threadIdx.x;
    if (i < NN) atomicAdd(&g_pcnt[p][batch[i]], 1);
}

// ---------------- layer-0 input aggregation: aggx = Â x  (fp16, MLP=4) ---------
__global__ void __launch_bounds__(256)
pullx_kernel(const __half* __restrict__ xh, float* __restrict__ aggx, int p)
{
    int n = (int)((blockIdx.x * (unsigned)blockDim.x + threadIdx.x) >> 5);
    int lane = threadIdx.x & 31;
    if (n >= NN) return;
    int c = lane * 4;

    float d2 = g_dinv2[p][n];
    uint2 sv = *reinterpret_cast<const uint2*>(xh + (size_t)n * FIN + c);
    float2 s0 = __half22float2(*reinterpret_cast<__half2*>(&sv.x));
    float2 s1 = __half22float2(*reinterpret_cast<__half2*>(&sv.y));
    float4 acc = make_float4(s0.x * d2, s0.y * d2, s1.x * d2, s1.y * d2);

    int e = g_rowptr[p][n];
    int end = g_rowptr[p][n + 1];
    const int2* ep = g_epack[p];

    for (; e + 3 < end; e += 4) {
        int2 p0 = ep[e + 0];
        int2 p1 = ep[e + 1];
        int2 p2 = ep[e + 2];
        int2 p3 = ep[e + 3];
        uint2 v0 = *reinterpret_cast<const uint2*>(xh + (size_t)p0.x * FIN + c);
        uint2 v1 = *reinterpret_cast<const uint2*>(xh + (size_t)p1.x * FIN + c);
        uint2 v2 = *reinterpret_cast<const uint2*>(xh + (size_t)p2.x * FIN + c);
        uint2 v3 = *reinterpret_cast<const uint2*>(xh + (size_t)p3.x * FIN + c);
        hacc2(acc, __int_as_float(p0.y), v0);
        hacc2(acc, __int_as_float(p1.y), v1);
        hacc2(acc, __int_as_float(p2.y), v2);
        hacc2(acc, __int_as_float(p3.y), v3);
    }
    for (; e < end; e++) {
        int2 pe = ep[e];
        uint2 v = *reinterpret_cast<const uint2*>(xh + (size_t)pe.x * FIN + c);
        hacc2(acc, __int_as_float(pe.y), v);
    }

    *reinterpret_cast<float4*>(aggx + (size_t)n * FIN + c) = acc;
}

// ---------------- GEMM: out = act(A) @ W (+bias | fp16)  (FFMA2 128x128) ------
template <int K, bool RELU, bool BIAS, bool HALFOUT>
__global__ void __launch_bounds__(256, 2)
gemm2_kernel(const float* __restrict__ A, const float* __restrict__ W,
             const float* __restrict__ bias, float* __restrict__ HoutF,
             __half* __restrict__ HoutH)
{
    __shared__ float As[16][132];
    __shared__ float Bs[16][128];

    const int t  = threadIdx.x;
    const int tx = t & 15;
    const int ty = t >> 4;
    const int rowBase = blockIdx.x * 128;
    const int colBase = blockIdx.y * 128;

    const int arow = t >> 2;
    const int akg  = (t & 3) * 4;
    const int brow = t >> 5;
    const int bcol = (t & 31) * 4;

    const int r0 = rowBase + arow;
    const int r1 = r0 + 64;

    u64 acc[8][4];
#pragma unroll
    for (int i = 0; i < 8; i++)
#pragma unroll
        for (int j = 0; j < 4; j++) acc[i][j] = 0ull;

    float4 pa0, pa1, pb0, pb1;
    {
        pa0 = make_float4(0.f, 0.f, 0.f, 0.f); pa1 = pa0;
        if (r0 < NN) pa0 = *reinterpret_cast<const float4*>(A + (size_t)r0 * K + akg);
        if (r1 < NN) pa1 = *reinterpret_cast<const float4*>(A + (size_t)r1 * K + akg);
        pb0 = *reinterpret_cast<const float4*>(W + (size_t)brow * HH + colBase + bcol);
        pb1 = *reinterpret_cast<const float4*>(W + (size_t)(8 + brow) * HH + colBase + bcol);
    }

    for (int k0 = 0; k0 < K; k0 += 16) {
        float4 a0 = pa0, a1 = pa1, b0 = pb0, b1 = pb1;
        if (RELU) {
            a0.x = fmaxf(a0.x, 0.f); a0.y = fmaxf(a0.y, 0.f);
            a0.z = fmaxf(a0.z, 0.f); a0.w = fmaxf(a0.w, 0.f);
            a1.x = fmaxf(a1.x, 0.f); a1.y = fmaxf(a1.y, 0.f);
            a1.z = fmaxf(a1.z, 0.f); a1.w = fmaxf(a1.w, 0.f);
        }
        As[akg + 0][arow] = a0.x; As[akg + 1][arow] = a0.y;
        As[akg + 2][arow] = a0.z; As[akg + 3][arow] = a0.w;
        As[akg + 0][64 + arow] = a1.x; As[akg + 1][64 + arow] = a1.y;
        As[akg + 2][64 + arow] = a1.z; As[akg + 3][64 + arow] = a1.w;
        *reinterpret_cast<float4*>(&Bs[brow][bcol])     = b0;
        *reinterpret_cast<float4*>(&Bs[brow + 8][bcol]) = b1;
        __syncthreads();

        if (k0 + 16 < K) {
            int kn = k0 + 16;
            pa0 = make_float4(0.f, 0.f, 0.f, 0.f); pa1 = pa0;
            if (r0 < NN) pa0 = *reinterpret_cast<const float4*>(A + (size_t)r0 * K + kn + akg);
            if (r1 < NN) pa1 = *reinterpret_cast<const float4*>(A + (size_t)r1 * K + kn + akg);
            pb0 = *reinterpret_cast<const float4*>(W + (size_t)(kn + brow) * HH + colBase + bcol);
            pb1 = *reinterpret_cast<const float4*>(W + (size_t)(kn + 8 + brow) * HH + colBase + bcol);
        }

#pragma unroll
        for (int kk = 0; kk < 16; kk++) {
            float4 av0 = *reinterpret_cast<const float4*>(&As[kk][ty * 4]);
            float4 av1 = *reinterpret_cast<const float4*>(&As[kk][64 + ty * 4]);
            ulonglong2 bv0 = *reinterpret_cast<const ulonglong2*>(&Bs[kk][tx * 4]);
            ulonglong2 bv1 = *reinterpret_cast<const ulonglong2*>(&Bs[kk][64 + tx * 4]);
            u64 aa;
            aa = dup2(av0.x);
            fma2(acc[0][0], aa, bv0.x); fma2(acc[0][1], aa, bv0.y);
            fma2(acc[0][2], aa, bv1.x); fma2(acc[0][3], aa, bv1.y);
            aa = dup2(av0.y);
            fma2(acc[1][0], aa, bv0.x); fma2(acc[1][1], aa, bv0.y);
            fma2(acc[1][2], aa, bv1.x); fma2(acc[1][3], aa, bv1.y);
            aa = dup2(av0.z);
            fma2(acc[2][0], aa, bv0.x); fma2(acc[2][1], aa, bv0.y);
            fma2(acc[2][2], aa, bv1.x); fma2(acc[2][3], aa, bv1.y);
            aa = dup2(av0.w);
            fma2(acc[3][0], aa, bv0.x); fma2(acc[3][1], aa, bv0.y);
            fma2(acc[3][2], aa, bv1.x); fma2(acc[3][3], aa, bv1.y);
            aa = dup2(av1.x);
            fma2(acc[4][0], aa, bv0.x); fma2(acc[4][1], aa, bv0.y);
            fma2(acc[4][2], aa, bv1.x); fma2(acc[4][3], aa, bv1.y);
            aa = dup2(av1.y);
            fma2(acc[5][0], aa, bv0.x); fma2(acc[5][1], aa, bv0.y);
            fma2(acc[5][2], aa, bv1.x); fma2(acc[5][3], aa, bv1.y);
            aa = dup2(av1.z);
            fma2(acc[6][0], aa, bv0.x); fma2(acc[6][1], aa, bv0.y);
            fma2(acc[6][2], aa, bv1.x); fma2(acc[6][3], aa, bv1.y);
            aa = dup2(av1.w);
            fma2(acc[7][0], aa, bv0.x); fma2(acc[7][1], aa, bv0.y);
            fma2(acc[7][2], aa, bv1.x); fma2(acc[7][3], aa, bv1.y);
        }
        __syncthreads();
    }

    float4 bias0 = make_float4(0.f, 0.f, 0.f, 0.f), bias1 = bias0;
    if (BIAS) {
        bias0 = *reinterpret_cast<const float4*>(bias + colBase + tx * 4);
        bias1 = *reinterpret_cast<const float4*>(bias + colBase + 64 + tx * 4);
    }
#pragma unroll
    for (int i = 0; i < 8; i++) {
        int r = rowBase + ((i < 4) ? (ty * 4 + i) : (64 + ty * 4 + (i - 4)));
        if (r < NN) {
            float2 c0 = unp2(acc[i][0]), c1 = unp2(acc[i][1]);
            float2 c2 = unp2(acc[i][2]), c3 = unp2(acc[i][3]);
            float4 o0 = make_float4(c0.x, c0.y, c1.x, c1.y);
            float4 o1 = make_float4(c2.x, c2.y, c3.x, c3.y);
            if (BIAS) {
                o0.x += bias0.x; o0.y += bias0.y; o0.z += bias0.z; o0.w += bias0.w;
                o1.x += bias1.x; o1.y += bias1.y; o1.z += bias1.z; o1.w += bias1.w;
            }
            if (HALFOUT) {
                __half2 h0 = __float22half2_rn(make_float2(o0.x, o0.y));
                __half2 h1 = __float22half2_rn(make_float2(o0.z, o0.w));
                __half2 h2 = __float22half2_rn(make_float2(o1.x, o1.y));
                __half2 h3 = __float22half2_rn(make_float2(o1.z, o1.w));
                uint2 s0, s1;
                s0.x = *reinterpret_cast<uint32_t*>(&h0);
                s0.y = *reinterpret_cast<uint32_t*>(&h1);
                s1.x = *reinterpret_cast<uint32_t*>(&h2);
                s1.y = *reinterpret_cast<uint32_t*>(&h3);
                *reinterpret_cast<uint2*>(HoutH + (size_t)r * HH + colBase + tx * 4) = s0;
                *reinterpret_cast<uint2*>(HoutH + (size_t)r * HH + colBase + 64 + tx * 4) = s1;
            } else {
                *reinterpret_cast<float4*>(HoutF + (size_t)r * HH + colBase + tx * 4) = o0;
                *reinterpret_cast<float4*>(HoutF + (size_t)r * HH + colBase + 64 + tx * 4) = o1;
            }
        }
    }
}

// ---------------- pull aggregation (fp16 gather, 256 cols/warp, MLP=4) ---------
__global__ void __launch_bounds__(256)
pull_kernel(const float* __restrict__ bias, const __half* __restrict__ h,
            float* __restrict__ out, const int* __restrict__ batch,
            int doPool, int p)
{
    int n = (int)((blockIdx.x * (unsigned)blockDim.x + threadIdx.x) >> 5);
    int lane = threadIdx.x & 31;
    if (n >= NN) return;
    int c = lane * 8;  // 8 cols per lane (uint4 = 8 halves)

    float d2 = g_dinv2[p][n];
    float4 ba = *reinterpret_cast<const float4*>(bias + c);
    float4 bb = *reinterpret_cast<const float4*>(bias + c + 4);
    float4 accA = make_float4(0.f, 0.f, 0.f, 0.f);
    float4 accB = make_float4(0.f, 0.f, 0.f, 0.f);
    {
        uint4 sv = *reinterpret_cast<const uint4*>(h + (size_t)n * HH + c);
        hacc4(accA, accB, d2, sv);
        accA.x += ba.x; accA.y += ba.y; accA.z += ba.z; accA.w += ba.w;
        accB.x += bb.x; accB.y += bb.y; accB.z += bb.z; accB.w += bb.w;
    }

    int e = g_rowptr[p][n];
    int end = g_rowptr[p][n + 1];
    const int2* ep = g_epack[p];

    for (; e + 3 < end; e += 4) {
        int2 p0 = ep[e + 0];
        int2 p1 = ep[e + 1];
        int2 p2 = ep[e + 2];
        int2 p3 = ep[e + 3];
        uint4 v0 = *reinterpret_cast<const uint4*>(h + (size_t)p0.x * HH + c);
        uint4 v1 = *reinterpret_cast<const uint4*>(h + (size_t)p1.x * HH + c);
        uint4 v2 = *reinterpret_cast<const uint4*>(h + (size_t)p2.x * HH + c);
        uint4 v3 = *reinterpret_cast<const uint4*>(h + (size_t)p3.x * HH + c);
        hacc4(accA, accB, __int_as_float(p0.y), v0);
        hacc4(accA, accB, __int_as_float(p1.y), v1);
        hacc4(accA, accB, __int_as_float(p2.y), v2);
        hacc4(accA, accB, __int_as_float(p3.y), v3);
    }
    for (; e < end; e++) {
        int2 pe = ep[e];
        uint4 v = *reinterpret_cast<const uint4*>(h + (size_t)pe.x * HH + c);
        hacc4(accA, accB, __int_as_float(pe.y), v);
    }

    if (!doPool) {
        *reinterpret_cast<float4*>(out + (size_t)n * HH + c)     = accA;
        *reinterpret_cast<float4*>(out + (size_t)n * HH + c + 4) = accB;
    } else {
        int g = __ldg(&batch[n]);
        red_add_v4(reinterpret_cast<float4*>(g_psum[p] + g * HH + c), accA);
        red_add_v4(reinterpret_cast<float4*>(g_psum[p] + g * HH + c + 4), accB);
    }
}

// ---------------- z = mean @ lin0_W + lin0_b -----------------------------------
__global__ void __launch_bounds__(128)
z_kernel(const float* __restrict__ lin0W, const float* __restrict__ lin0b,
         float* __restrict__ outz, int p)
{
    __shared__ float mean[HH];
    int g = blockIdx.x;
    int t = threadIdx.x;
    float c = fmaxf((float)g_pcnt[p][g], 1.0f);
    mean[t]       = g_psum[p][g * HH + t] / c;
    mean[t + 128] = g_psum[p][g * HH + t + 128] / c;
    __syncthreads();
    float acc = lin0b[t];
#pragma unroll 8
    for (int k = 0; k < HH; k++)
        acc = fmaf(mean[k], __ldg(&lin0W[(size_t)k * HO + t]), acc);
    outz[g * HO + t] = acc;
}

// ---------------- triplet head ------------------------------------------------
__global__ void final_kernel(const float* __restrict__ linW,
                             const float* __restrict__ linb,
                             float* __restrict__ out)
{
    __shared__ int s1, s2;
    int g = threadIdx.x;
    if (g == 0) { s1 = 0; s2 = 0; }
    __syncthreads();

    const float* z0 = out;
    const float* z1 = out + GG * HO;
    const float* z2 = out + 2 * GG * HO;
    const float EPS = 1e-6f;

    float dp = 0.f, dn = 0.f;
    float y1 = linb[0], y2 = linb[0];
#pragma unroll 4
    for (int j = 0; j < HO; j++) {
        float a = z0[g * HO + j];
        float b = z1[g * HO + j];
        float c = z2[g * HO + j];
        float e1 = a - b + EPS; dp = fmaf(e1, e1, dp);
        float e2 = a - c + EPS; dn = fmaf(e2, e2, dn);
        float wa = linW[j], wb = linW[HO + j];
        y1 = fmaf(a, wa, fmaf(b, wb, y1));
        y2 = fmaf(a, wa, fmaf(c, wb, y2));
    }
    dp = sqrtf(dp); dn = sqrtf(dn);
    float sp = 1.0f / (1.0f + expf(-y1));
    float sn = 1.0f / (1.0f + expf(-y2));

    const int base = 3 * GG * HO;
    out[base + 1 + g] = sp;
    out[base + 1 + GG + g] = sn;
    if (dn - dp > 0.f) atomicAdd(&s1, 1);
    if (sp - sn > 0.f) atomicAdd(&s2, 1);
    __syncthreads();
    if (g == 0) {
        out[base] = (float)s1;
        out[base + 1 + 2 * GG] = (float)s2;
    }
}

// ---------------- host orchestration ------------------------------------------
extern "C" void kernel_launch(void* const* d_in, const int* in_sizes, int n_in,
                              void* d_out, int out_size)
{
    const float* x[3]     = { (const float*)d_in[0], (const float*)d_in[1], (const float*)d_in[2] };
    const int*   ei[3]    = { (const int*)d_in[3], (const int*)d_in[4], (const int*)d_in[5] };
    const int*   batch[3] = { (const int*)d_in[6], (const int*)d_in[7], (const int*)d_in[8] };
    const float* W0 = (const float*)d_in[9];
    const float* b0 = (const float*)d_in[10];
    const float* W1 = (const float*)d_in[11];
    const float* b1 = (const float*)d_in[12];
    const float* W2 = (const float*)d_in[13];
    const float* b2 = (const float*)d_in[14];
    const float* lin0W = (const float*)d_in[15];
    const float* lin0b = (const float*)d_in[16];
    const float* linW  = (const float*)d_in[17];
    const float* linb  = (const float*)d_in[18];
    float* out = (float*)d_out;

    static cudaStream_t st[3];
    static cudaEvent_t evRoot, evDone[3];
    static bool inited = false;
    if (!inited) {
        for (int i = 0; i < 3; i++) cudaStreamCreateWithFlags(&st[i], cudaStreamNonBlocking);
        cudaEventCreateWithFlags(&evRoot, cudaEventDisableTiming);
        for (int i = 0; i < 3; i++) cudaEventCreateWithFlags(&evDone[i], cudaEventDisableTiming);
        inited = true;
    }

    float *p0ptr[3], *p1ptr[3];
    __half *hhptr[3], *xhptr[3];
    {
        float* base;
        cudaGetSymbolAddress((void**)&base, g_p0);
        for (int i = 0; i < 3; i++) p0ptr[i] = base + (size_t)i * NH;
        cudaGetSymbolAddress((void**)&base, g_p1);
        for (int i = 0; i < 3; i++) p1ptr[i] = base + (size_t)i * NH;
        __half* hb;
        cudaGetSymbolAddress((void**)&hb, g_hh);
        for (int i = 0; i < 3; i++) hhptr[i] = hb + (size_t)i * NH;
        cudaGetSymbolAddress((void**)&hb, g_xh);
        for (int i = 0; i < 3; i++) xhptr[i] = hb + (size_t)i * NN * FIN;
    }

    dim3 gemmGrid((NN + 127) / 128, HH / 128);
    int  warpBlocks = (int)(((long long)NN * 32 + 255) / 256);
    const int NB = (NN + 1023) / 1024;
    int  xcvtBlocks = (int)(((size_t)NN * FIN / 4 + 255) / 256);

    cudaEventRecord(evRoot, 0);

    for (int p = 0; p < 3; p++) {
        cudaStream_t s = st[p];
        cudaStreamWaitEvent(s, evRoot, 0);

        const int* srcp = ei[p];
        const int* dstp = ei[p] + EE;

        // ---- per-pass graph prep + x conversion ----
        zero_kernel<<<(NN + 255) / 256, 256, 0, s>>>(p);
        xcvt_kernel<<<xcvtBlocks, 256, 0, s>>>(x[p], xhptr[p]);
        deg_kernel<<<(EE + 255) / 256, 256, 0, s>>>(dstp, p);
        dinv_kernel<<<(NN + 255) / 256, 256, 0, s>>>(p);
        scan1_kernel<<<NB, 1024, 0, s>>>(p);
        scan2_kernel<<<1, 128, 0, s>>>(p);
        scan3_kernel<<<(NN + 255) / 256, 256, 0, s>>>(p);
        csr_kernel<<<(EE + 255) / 256, 256, 0, s>>>(srcp, dstp, p);
        pcnt_kernel<<<(NN + 255) / 256, 256, 0, s>>>(batch[p], p);

        // ---- layer 0 (aggregate-first): aggx = Â x -> p1 ; p0 = aggx@W0 + b0
        pullx_kernel<<<warpBlocks, 256, 0, s>>>(xhptr[p], p1ptr[p], p);
        gemm2_kernel<FIN, false, true, false><<<gemmGrid, 256, 0, s>>>(
            p1ptr[p], W0, b0, p0ptr[p], nullptr);

        // ---- layer 1: hh = relu(p0)@W1 (fp16) ; pull+b1 -> p1
        gemm2_kernel<HH, true, false, true><<<gemmGrid, 256, 0, s>>>(
            p0ptr[p], W1, nullptr, nullptr, hhptr[p]);
        pull_kernel<<<warpBlocks, 256, 0, s>>>(b1, hhptr[p], p1ptr[p], nullptr, 0, p);

        // ---- layer 2: hh = relu(p1)@W2 (fp16) ; pull+b2 -> pooled only
        gemm2_kernel<HH, true, false, true><<<gemmGrid, 256, 0, s>>>(
            p1ptr[p], W2, nullptr, nullptr, hhptr[p]);
        pull_kernel<<<warpBlocks, 256, 0, s>>>(b2, hhptr[p], nullptr, batch[p], 1, p);

        // ---- z_p = mean @ lin0_W + lin0_b
        z_kernel<<<GG, 128, 0, s>>>(lin0W, lin0b, out + (size_t)p * GG * HO, p);

        cudaEventRecord(evDone[p], s);
    }

    for (int p = 0; p < 3; p++) cudaStreamWaitEvent(0, evDone[p], 0);

    final_kernel<<<1, GG>>>(linW, linb, out);
}

// round 10
// speedup vs baseline: 1.1111x; 1.0242x over previous
#include <cuda_runtime.h>
#include <cuda_bf16.h>
#include <cuda_fp16.h>
#include <stdint.h>
#include <math.h>

// Problem constants (fixed by the dataset)
#define NN 100000
#define EE 3200000
#define FIN 128
#define HH  256
#define GG  64
#define HO  128   // H/2

typedef unsigned long long u64;

// ---------------- per-pass scratch (static device globals) --------------------
#define NH ((size_t)NN * HH)
__device__ __align__(16) __half g_hh [3][NH];                 // GEMM out (gather source)
__device__ __align__(16) __half g_a  [3][NH];                 // GEMM A input (pull output)
__device__ __align__(16) __half g_xh [3][(size_t)NN * FIN];   // fp16 x
__device__ __align__(16) __half g_agg[3][(size_t)NN * FIN];   // layer-0 agg out
__device__ float g_dinv [3][NN];
__device__ float g_dinv2[3][NN];
__device__ int   g_deg  [3][NN];
__device__ __align__(16) float g_psum[3][GG * HH];
__device__ int   g_pcnt[3][GG];
__device__ int   g_rowptr[3][NN + 1];
__device__ int   g_off[3][NN];
__device__ int   g_bsum[3][128];
__device__ int   g_bsum2[3][128];
__device__ __align__(16) int2 g_epack[3][EE];   // (src, coef-as-int)

// ---------------- helpers ----------------------------------------------------
__device__ __forceinline__ void red_add_v4(float4* addr, float4 v) {
    asm volatile("red.global.add.v4.f32 [%0], {%1,%2,%3,%4};"
                 :: "l"(addr), "f"(v.x), "f"(v.y), "f"(v.z), "f"(v.w)
                 : "memory");
}
__device__ __forceinline__ u64 dup2(float a) {
    u64 r; asm("mov.b64 %0, {%1, %1};" : "=l"(r) : "f"(a)); return r;
}
__device__ __forceinline__ void fma2(u64& acc, u64 a, u64 b) {
    asm("fma.rn.f32x2 %0, %1, %2, %0;" : "+l"(acc) : "l"(a), "l"(b));
}
__device__ __forceinline__ float2 unp2(u64 v) {
    float2 f; asm("mov.b64 {%0, %1}, %2;" : "=f"(f.x), "=f"(f.y) : "l"(v)); return f;
}
__device__ __forceinline__ void hacc4(float4& a0, float4& a1, float cf, const uint4& v) {
    float2 x0 = __half22float2(*reinterpret_cast<const __half2*>(&v.x));
    float2 x1 = __half22float2(*reinterpret_cast<const __half2*>(&v.y));
    float2 x2 = __half22float2(*reinterpret_cast<const __half2*>(&v.z));
    float2 x3 = __half22float2(*reinterpret_cast<const __half2*>(&v.w));
    a0.x = fmaf(cf, x0.x, a0.x); a0.y = fmaf(cf, x0.y, a0.y);
    a0.z = fmaf(cf, x1.x, a0.z); a0.w = fmaf(cf, x1.y, a0.w);
    a1.x = fmaf(cf, x2.x, a1.x); a1.y = fmaf(cf, x2.y, a1.y);
    a1.z = fmaf(cf, x3.x, a1.z); a1.w = fmaf(cf, x3.y, a1.w);
}
__device__ __forceinline__ void hacc2(float4& a, float cf, const uint2& v) {
    float2 x0 = __half22float2(*reinterpret_cast<const __half2*>(&v.x));
    float2 x1 = __half22float2(*reinterpret_cast<const __half2*>(&v.y));
    a.x = fmaf(cf, x0.x, a.x); a.y = fmaf(cf, x0.y, a.y);
    a.z = fmaf(cf, x1.x, a.z); a.w = fmaf(cf, x1.y, a.w);
}
__device__ __forceinline__ uint2 pack_half4(float4 v) {
    __half2 h0 = __float22half2_rn(make_float2(v.x, v.y));
    __half2 h1 = __float22half2_rn(make_float2(v.z, v.w));
    uint2 s;
    s.x = *reinterpret_cast<uint32_t*>(&h0);
    s.y = *reinterpret_cast<uint32_t*>(&h1);
    return s;
}
__device__ __forceinline__ float4 unpack_half4(uint2 s) {
    float2 a = __half22float2(*reinterpret_cast<const __half2*>(&s.x));
    float2 b = __half22float2(*reinterpret_cast<const __half2*>(&s.y));
    return make_float4(a.x, a.y, b.x, b.y);
}

// ---------------- per-pass setup ---------------------------------------------
__global__ void zero_kernel(int p) {
    int i = blockIdx.x * blockDim.x + threadIdx.x;
    if (i < NN)      { g_deg[p][i] = 0; g_off[p][i] = 0; }
    if (i < GG * HH) g_psum[p][i] = 0.f;
    if (i < GG)      g_pcnt[p][i] = 0;
}

__global__ void deg_kernel(const int* __restrict__ dst, int p) {
    int e = blockIdx.x * blockDim.x + threadIdx.x;
    if (e < EE) atomicAdd(&g_deg[p][dst[e]], 1);
}

__global__ void dinv_kernel(int p) {
    int i = blockIdx.x * blockDim.x + threadIdx.x;
    if (i < NN) {
        float d = (float)g_deg[p][i] + 1.0f;
        g_dinv[p][i]  = rsqrtf(d);
        g_dinv2[p][i] = 1.0f / d;
    }
}

// x fp32 -> fp16
__global__ void xcvt_kernel(const float* __restrict__ x, __half* __restrict__ xh) {
    size_t i = ((size_t)blockIdx.x * blockDim.x + threadIdx.x) * 4;
    if (i >= (size_t)NN * FIN) return;
    float4 v = *reinterpret_cast<const float4*>(x + i);
    *reinterpret_cast<uint2*>(xh + i) = pack_half4(v);
}

// ---------------- exclusive scan of deg -> rowptr ------------------------------
__global__ void scan1_kernel(int p) {
    __shared__ int s[1024];
    int t = threadIdx.x;
    int i = blockIdx.x * 1024 + t;
    int v = (i < NN) ? g_deg[p][i] : 0;
    int x = v;
    s[t] = x;
    __syncthreads();
#pragma unroll
    for (int off = 1; off < 1024; off <<= 1) {
        int y = (t >= off) ? s[t - off] : 0;
        __syncthreads();
        x += y;
        s[t] = x;
        __syncthreads();
    }
    if (i < NN) g_rowptr[p][i] = x - v;
    if (t == 1023) g_bsum[p][blockIdx.x] = x;
}

__global__ void scan2_kernel(int p) {
    __shared__ int s[128];
    int t = threadIdx.x;
    const int NB = (NN + 1023) >> 10;
    int v = (t < NB) ? g_bsum[p][t] : 0;
    int x = v;
    s[t] = x;
    __syncthreads();
#pragma unroll
    for (int off = 1; off < 128; off <<= 1) {
        int y = (t >= off) ? s[t - off] : 0;
        __syncthreads();
        x += y;
        s[t] = x;
        __syncthreads();
    }
    g_bsum2[p][t] = x - v;
}

__global__ void scan3_kernel(int p) {
    int i = blockIdx.x * blockDim.x + threadIdx.x;
    if (i < NN) g_rowptr[p][i] += g_bsum2[p][i >> 10];
    if (i == 0) g_rowptr[p][NN] = EE;
}

__global__ void csr_kernel(const int* __restrict__ src, const int* __restrict__ dst, int p) {
    int e = blockIdx.x * blockDim.x + threadIdx.x;
    if (e >= EE) return;
    int s = src[e], d = dst[e];
    float coef = g_dinv[p][s] * g_dinv[p][d];
    int pos = g_rowptr[p][d] + atomicAdd(&g_off[p][d], 1);
    g_epack[p][pos] = make_int2(s, __float_as_int(coef));
}

__global__ void pcnt_kernel(const int* __restrict__ batch, int p) {
    int i = blockIdx.x * blockDim.x + threadIdx.x;
    if (i < NN) atomicAdd(&g_pcnt[p][batch[i]], 1);
}

// ---------------- layer-0 input aggregation: agg = Â x (fp16 in/out, MLP=8) ----
__global__ void __launch_bounds__(256)
pullx_kernel(const __half* __restrict__ xh, __half* __restrict__ agg, int p)
{
    int n = (int)((blockIdx.x * (unsigned)blockDim.x + threadIdx.x) >> 5);
    int lane = threadIdx.x & 31;
    if (n >= NN) return;
    int c = lane * 4;

    float d2 = g_dinv2[p][n];
    float4 sv = unpack_half4(*reinterpret_cast<const uint2*>(xh + (size_t)n * FIN + c));
    float4 acc = make_float4(sv.x * d2, sv.y * d2, sv.z * d2, sv.w * d2);

    int e = g_rowptr[p][n];
    int end = g_rowptr[p][n + 1];
    const int2* ep = g_epack[p];

    for (; e + 7 < end; e += 8) {
        int2 pe[8];
        uint2 v[8];
#pragma unroll
        for (int j = 0; j < 8; j++) pe[j] = ep[e + j];
#pragma unroll
        for (int j = 0; j < 8; j++)
            v[j] = *reinterpret_cast<const uint2*>(xh + (size_t)pe[j].x * FIN + c);
#pragma unroll
        for (int j = 0; j < 8; j++)
            hacc2(acc, __int_as_float(pe[j].y), v[j]);
    }
    for (; e < end; e++) {
        int2 pe = ep[e];
        uint2 v = *reinterpret_cast<const uint2*>(xh + (size_t)pe.x * FIN + c);
        hacc2(acc, __int_as_float(pe.y), v);
    }

    *reinterpret_cast<uint2*>(agg + (size_t)n * FIN + c) = pack_half4(acc);
}

// ---------------- GEMM: out = act(A) @ W (+bias) ; A fp16, out fp16 -----------
template <int K, bool RELU, bool BIAS>
__global__ void __launch_bounds__(256, 2)
gemm2_kernel(const __half* __restrict__ A, const float* __restrict__ W,
             const float* __restrict__ bias, __half* __restrict__ Hout)
{
    __shared__ float As[16][132];
    __shared__ float Bs[16][128];

    const int t  = threadIdx.x;
    const int tx = t & 15;
    const int ty = t >> 4;
    const int rowBase = blockIdx.x * 128;
    const int colBase = blockIdx.y * 128;

    const int arow = t >> 2;
    const int akg  = (t & 3) * 4;
    const int brow = t >> 5;
    const int bcol = (t & 31) * 4;

    const int r0 = rowBase + arow;
    const int r1 = r0 + 64;

    u64 acc[8][4];
#pragma unroll
    for (int i = 0; i < 8; i++)
#pragma unroll
        for (int j = 0; j < 4; j++) acc[i][j] = 0ull;

    uint2 ra0, ra1;
    float4 pb0, pb1;
    {
        ra0 = make_uint2(0u, 0u); ra1 = ra0;
        if (r0 < NN) ra0 = *reinterpret_cast<const uint2*>(A + (size_t)r0 * K + akg);
        if (r1 < NN) ra1 = *reinterpret_cast<const uint2*>(A + (size_t)r1 * K + akg);
        pb0 = *reinterpret_cast<const float4*>(W + (size_t)brow * HH + colBase + bcol);
        pb1 = *reinterpret_cast<const float4*>(W + (size_t)(8 + brow) * HH + colBase + bcol);
    }

    for (int k0 = 0; k0 < K; k0 += 16) {
        float4 a0 = unpack_half4(ra0);
        float4 a1 = unpack_half4(ra1);
        float4 b0 = pb0, b1 = pb1;
        if (RELU) {
            a0.x = fmaxf(a0.x, 0.f); a0.y = fmaxf(a0.y, 0.f);
            a0.z = fmaxf(a0.z, 0.f); a0.w = fmaxf(a0.w, 0.f);
            a1.x = fmaxf(a1.x, 0.f); a1.y = fmaxf(a1.y, 0.f);
            a1.z = fmaxf(a1.z, 0.f); a1.w = fmaxf(a1.w, 0.f);
        }
        As[akg + 0][arow] = a0.x; As[akg + 1][arow] = a0.y;
        As[akg + 2][arow] = a0.z; As[akg + 3][arow] = a0.w;
        As[akg + 0][64 + arow] = a1.x; As[akg + 1][64 + arow] = a1.y;
        As[akg + 2][64 + arow] = a1.z; As[akg + 3][64 + arow] = a1.w;
        *reinterpret_cast<float4*>(&Bs[brow][bcol])     = b0;
        *reinterpret_cast<float4*>(&Bs[brow + 8][bcol]) = b1;
        __syncthreads();

        if (k0 + 16 < K) {
            int kn = k0 + 16;
            ra0 = make_uint2(0u, 0u); ra1 = ra0;
            if (r0 < NN) ra0 = *reinterpret_cast<const uint2*>(A + (size_t)r0 * K + kn + akg);
            if (r1 < NN) ra1 = *reinterpret_cast<const uint2*>(A + (size_t)r1 * K + kn + akg);
            pb0 = *reinterpret_cast<const float4*>(W + (size_t)(kn + brow) * HH + colBase + bcol);
            pb1 = *reinterpret_cast<const float4*>(W + (size_t)(kn + 8 + brow) * HH + colBase + bcol);
        }

#pragma unroll
        for (int kk = 0; kk < 16; kk++) {
            float4 av0 = *reinterpret_cast<const float4*>(&As[kk][ty * 4]);
            float4 av1 = *reinterpret_cast<const float4*>(&As[kk][64 + ty * 4]);
            ulonglong2 bv0 = *reinterpret_cast<const ulonglong2*>(&Bs[kk][tx * 4]);
            ulonglong2 bv1 = *reinterpret_cast<const ulonglong2*>(&Bs[kk][64 + tx * 4]);
            u64 aa;
            aa = dup2(av0.x);
            fma2(acc[0][0], aa, bv0.x); fma2(acc[0][1], aa, bv0.y);
            fma2(acc[0][2], aa, bv1.x); fma2(acc[0][3], aa, bv1.y);
            aa = dup2(av0.y);
            fma2(acc[1][0], aa, bv0.x); fma2(acc[1][1], aa, bv0.y);
            fma2(acc[1][2], aa, bv1.x); fma2(acc[1][3], aa, bv1.y);
            aa = dup2(av0.z);
            fma2(acc[2][0], aa, bv0.x); fma2(acc[2][1], aa, bv0.y);
            fma2(acc[2][2], aa, bv1.x); fma2(acc[2][3], aa, bv1.y);
            aa = dup2(av0.w);
            fma2(acc[3][0], aa, bv0.x); fma2(acc[3][1], aa, bv0.y);
            fma2(acc[3][2], aa, bv1.x); fma2(acc[3][3], aa, bv1.y);
            aa = dup2(av1.x);
            fma2(acc[4][0], aa, bv0.x); fma2(acc[4][1], aa, bv0.y);
            fma2(acc[4][2], aa, bv1.x); fma2(acc[4][3], aa, bv1.y);
            aa = dup2(av1.y);
            fma2(acc[5][0], aa, bv0.x); fma2(acc[5][1], aa, bv0.y);
            fma2(acc[5][2], aa, bv1.x); fma2(acc[5][3], aa, bv1.y);
            aa = dup2(av1.z);
            fma2(acc[6][0], aa, bv0.x); fma2(acc[6][1], aa, bv0.y);
            fma2(acc[6][2], aa, bv1.x); fma2(acc[6][3], aa, bv1.y);
            aa = dup2(av1.w);
            fma2(acc[7][0], aa, bv0.x); fma2(acc[7][1], aa, bv0.y);
            fma2(acc[7][2], aa, bv1.x); fma2(acc[7][3], aa, bv1.y);
        }
        __syncthreads();
    }

    float4 bias0 = make_float4(0.f, 0.f, 0.f, 0.f), bias1 = bias0;
    if (BIAS) {
        bias0 = *reinterpret_cast<const float4*>(bias + colBase + tx * 4);
        bias1 = *reinterpret_cast<const float4*>(bias + colBase + 64 + tx * 4);
    }
#pragma unroll
    for (int i = 0; i < 8; i++) {
        int r = rowBase + ((i < 4) ? (ty * 4 + i) : (64 + ty * 4 + (i - 4)));
        if (r < NN) {
            float2 c0 = unp2(acc[i][0]), c1 = unp2(acc[i][1]);
            float2 c2 = unp2(acc[i][2]), c3 = unp2(acc[i][3]);
            float4 o0 = make_float4(c0.x, c0.y, c1.x, c1.y);
            float4 o1 = make_float4(c2.x, c2.y, c3.x, c3.y);
            if (BIAS) {
                o0.x += bias0.x; o0.y += bias0.y; o0.z += bias0.z; o0.w += bias0.w;
                o1.x += bias1.x; o1.y += bias1.y; o1.z += bias1.z; o1.w += bias1.w;
            }
            *reinterpret_cast<uint2*>(Hout + (size_t)r * HH + colBase + tx * 4) = pack_half4(o0);
            *reinterpret_cast<uint2*>(Hout + (size_t)r * HH + colBase + 64 + tx * 4) = pack_half4(o1);
        }
    }
}

// ---------------- pull aggregation (fp16 in/out, 256 cols/warp, MLP=8) ---------
__global__ void __launch_bounds__(256)
pull_kernel(const float* __restrict__ bias, const __half* __restrict__ h,
            __half* __restrict__ out, const int* __restrict__ batch,
            int doPool, int p)
{
    int n = (int)((blockIdx.x * (unsigned)blockDim.x + threadIdx.x) >> 5);
    int lane = threadIdx.x & 31;
    if (n >= NN) return;
    int c = lane * 8;  // 8 cols per lane (uint4 = 8 halves)

    float d2 = g_dinv2[p][n];
    float4 ba = *reinterpret_cast<const float4*>(bias + c);
    float4 bb = *reinterpret_cast<const float4*>(bias + c + 4);
    float4 accA = ba, accB = bb;
    {
        uint4 sv = *reinterpret_cast<const uint4*>(h + (size_t)n * HH + c);
        hacc4(accA, accB, d2, sv);
    }

    int e = g_rowptr[p][n];
    int end = g_rowptr[p][n + 1];
    const int2* ep = g_epack[p];

    for (; e + 7 < end; e += 8) {
        int2 pe[8];
        uint4 v[8];
#pragma unroll
        for (int j = 0; j < 8; j++) pe[j] = ep[e + j];
#pragma unroll
        for (int j = 0; j < 8; j++)
            v[j] = *reinterpret_cast<const uint4*>(h + (size_t)pe[j].x * HH + c);
#pragma unroll
        for (int j = 0; j < 8; j++)
            hacc4(accA, accB, __int_as_float(pe[j].y), v[j]);
    }
    for (; e < end; e++) {
        int2 pe = ep[e];
        uint4 v = *reinterpret_cast<const uint4*>(h + (size_t)pe.x * HH + c);
        hacc4(accA, accB, __int_as_float(pe.y), v);
    }

    if (!doPool) {
        uint4 s;
        uint2 sa = pack_half4(accA), sb = pack_half4(accB);
        s.x = sa.x; s.y = sa.y; s.z = sb.x; s.w = sb.y;
        *reinterpret_cast<uint4*>(out + (size_t)n * HH + c) = s;
    } else {
        int g = __ldg(&batch[n]);
        red_add_v4(reinterpret_cast<float4*>(g_psum[p] + g * HH + c), accA);
        red_add_v4(reinterpret_cast<float4*>(g_psum[p] + g * HH + c + 4), accB);
    }
}

// ---------------- z = mean @ lin0_W + lin0_b -----------------------------------
__global__ void __launch_bounds__(128)
z_kernel(const float* __restrict__ lin0W, const float* __restrict__ lin0b,
         float* __restrict__ outz, int p)
{
    __shared__ float mean[HH];
    int g = blockIdx.x;
    int t = threadIdx.x;
    float c = fmaxf((float)g_pcnt[p][g], 1.0f);
    mean[t]       = g_psum[p][g * HH + t] / c;
    mean[t + 128] = g_psum[p][g * HH + t + 128] / c;
    __syncthreads();
    float acc = lin0b[t];
#pragma unroll 8
    for (int k = 0; k < HH; k++)
        acc = fmaf(mean[k], __ldg(&lin0W[(size_t)k * HO + t]), acc);
    outz[g * HO + t] = acc;
}

// ---------------- triplet head ------------------------------------------------
__global__ void final_kernel(const float* __restrict__ linW,
                             const float* __restrict__ linb,
                             float* __restrict__ out)
{
    __shared__ int s1, s2;
    int g = threadIdx.x;
    if (g == 0) { s1 = 0; s2 = 0; }
    __syncthreads();

    const float* z0 = out;
    const float* z1 = out + GG * HO;
    const float* z2 = out + 2 * GG * HO;
    const float EPS = 1e-6f;

    float dp = 0.f, dn = 0.f;
    float y1 = linb[0], y2 = linb[0];
#pragma unroll 4
    for (int j = 0; j < HO; j++) {
        float a = z0[g * HO + j];
        float b = z1[g * HO + j];
        float c = z2[g * HO + j];
        float e1 = a - b + EPS; dp = fmaf(e1, e1, dp);
        float e2 = a - c + EPS; dn = fmaf(e2, e2, dn);
        float wa = linW[j], wb = linW[HO + j];
        y1 = fmaf(a, wa, fmaf(b, wb, y1));
        y2 = fmaf(a, wa, fmaf(c, wb, y2));
    }
    dp = sqrtf(dp); dn = sqrtf(dn);
    float sp = 1.0f / (1.0f + expf(-y1));
    float sn = 1.0f / (1.0f + expf(-y2));

    const int base = 3 * GG * HO;
    out[base + 1 + g] = sp;
    out[base + 1 + GG + g] = sn;
    if (dn - dp > 0.f) atomicAdd(&s1, 1);
    if (sp - sn > 0.f) atomicAdd(&s2, 1);
    __syncthreads();
    if (g == 0) {
        out[base] = (float)s1;
        out[base + 1 + 2 * GG] = (float)s2;
    }
}

// ---------------- host orchestration ------------------------------------------
extern "C" void kernel_launch(void* const* d_in, const int* in_sizes, int n_in,
                              void* d_out, int out_size)
{
    const float* x[3]     = { (const float*)d_in[0], (const float*)d_in[1], (const float*)d_in[2] };
    const int*   ei[3]    = { (const int*)d_in[3], (const int*)d_in[4], (const int*)d_in[5] };
    const int*   batch[3] = { (const int*)d_in[6], (const int*)d_in[7], (const int*)d_in[8] };
    const float* W0 = (const float*)d_in[9];
    const float* b0 = (const float*)d_in[10];
    const float* W1 = (const float*)d_in[11];
    const float* b1 = (const float*)d_in[12];
    const float* W2 = (const float*)d_in[13];
    const float* b2 = (const float*)d_in[14];
    const float* lin0W = (const float*)d_in[15];
    const float* lin0b = (const float*)d_in[16];
    const float* linW  = (const float*)d_in[17];
    const float* linb  = (const float*)d_in[18];
    float* out = (float*)d_out;

    static cudaStream_t st[3];
    static cudaEvent_t evRoot, evDone[3];
    static bool inited = false;
    if (!inited) {
        for (int i = 0; i < 3; i++) cudaStreamCreateWithFlags(&st[i], cudaStreamNonBlocking);
        cudaEventCreateWithFlags(&evRoot, cudaEventDisableTiming);
        for (int i = 0; i < 3; i++) cudaEventCreateWithFlags(&evDone[i], cudaEventDisableTiming);
        inited = true;
    }

    __half *hhptr[3], *aptr[3], *xhptr[3], *aggptr[3];
    {
        __half* hb;
        cudaGetSymbolAddress((void**)&hb, g_hh);
        for (int i = 0; i < 3; i++) hhptr[i] = hb + (size_t)i * NH;
        cudaGetSymbolAddress((void**)&hb, g_a);
        for (int i = 0; i < 3; i++) aptr[i] = hb + (size_t)i * NH;
        cudaGetSymbolAddress((void**)&hb, g_xh);
        for (int i = 0; i < 3; i++) xhptr[i] = hb + (size_t)i * NN * FIN;
        cudaGetSymbolAddress((void**)&hb, g_agg);
        for (int i = 0; i < 3; i++) aggptr[i] = hb + (size_t)i * NN * FIN;
    }

    dim3 gemmGrid((NN + 127) / 128, HH / 128);
    int  warpBlocks = (int)(((long long)NN * 32 + 255) / 256);
    const int NB = (NN + 1023) / 1024;
    int  xcvtBlocks = (int)(((size_t)NN * FIN / 4 + 255) / 256);

    cudaEventRecord(evRoot, 0);

    for (int p = 0; p < 3; p++) {
        cudaStream_t s = st[p];
        cudaStreamWaitEvent(s, evRoot, 0);

        const int* srcp = ei[p];
        const int* dstp = ei[p] + EE;

        // ---- per-pass graph prep + x conversion ----
        zero_kernel<<<(NN + 255) / 256, 256, 0, s>>>(p);
        xcvt_kernel<<<xcvtBlocks, 256, 0, s>>>(x[p], xhptr[p]);
        deg_kernel<<<(EE + 255) / 256, 256, 0, s>>>(dstp, p);
        dinv_kernel<<<(NN + 255) / 256, 256, 0, s>>>(p);
        scan1_kernel<<<NB, 1024, 0, s>>>(p);
        scan2_kernel<<<1, 128, 0, s>>>(p);
        scan3_kernel<<<(NN + 255) / 256, 256, 0, s>>>(p);
        csr_kernel<<<(EE + 255) / 256, 256, 0, s>>>(srcp, dstp, p);
        pcnt_kernel<<<(NN + 255) / 256, 256, 0, s>>>(batch[p], p);

        // ---- layer 0: agg = Â x (fp16) ; a = agg @ W0 + b0 (fp16)
        pullx_kernel<<<warpBlocks, 256, 0, s>>>(xhptr[p], aggptr[p], p);
        gemm2_kernel<FIN, false, true><<<gemmGrid, 256, 0, s>>>(aggptr[p], W0, b0, aptr[p]);

        // ---- layer 1: hh = relu(a) @ W1 ; pull+b1 -> a (fp16)
        gemm2_kernel<HH, true, false><<<gemmGrid, 256, 0, s>>>(aptr[p], W1, nullptr, hhptr[p]);
        pull_kernel<<<warpBlocks, 256, 0, s>>>(b1, hhptr[p], aptr[p], nullptr, 0, p);

        // ---- layer 2: hh = relu(a) @ W2 ; pull+b2 -> pooled psum
        gemm2_kernel<HH, true, false><<<gemmGrid, 256, 0, s>>>(aptr[p], W2, nullptr, hhptr[p]);
        pull_kernel<<<warpBlocks, 256, 0, s>>>(b2, hhptr[p], nullptr, batch[p], 1, p);

        // ---- z_p = mean @ lin0_W + lin0_b
        z_kernel<<<GG, 128, 0, s>>>(lin0W, lin0b, out + (size_t)p * GG * HO, p);

        cudaEventRecord(evDone[p], s);
    }

    for (int p = 0; p < 3; p++) cudaStreamWaitEvent(0, evDone[p], 0);

    final_kernel<<<1, GG>>>(linW, linb, out);
}

// round 11
// speedup vs baseline: 1.6179x; 1.4562x over previous
#include <cuda_runtime.h>
#include <cuda_bf16.h>
#include <cuda_fp16.h>
#include <stdint.h>
#include <math.h>

// Problem constants (fixed by the dataset)
#define NN 100000
#define EE 3200000
#define FIN 128
#define HH  256
#define GG  64
#define HO  128   // H/2

typedef unsigned long long u64;

// ---------------- per-pass scratch (static device globals) --------------------
#define NH ((size_t)NN * HH)
__device__ __align__(16) __half g_hh [3][NH];                 // GEMM out (gather source)
__device__ __align__(16) __half g_a  [3][NH];                 // GEMM A input (pull output)
__device__ __align__(16) __half g_xh [3][(size_t)NN * FIN];   // fp16 x
__device__ __align__(16) __half g_agg[3][(size_t)NN * FIN];   // layer-0 agg out
__device__ __align__(16) __half g_wt [256 * HH * 2 + 256 * FIN]; // fp16 WT: W1,W2 [256][256], W0 [256][128]
__device__ float g_dinv [3][NN];
__device__ float g_dinv2[3][NN];
__device__ int   g_deg  [3][NN];
__device__ __align__(16) float g_psum[3][GG * HH];
__device__ int   g_pcnt[3][GG];
__device__ int   g_rowptr[3][NN + 1];
__device__ int   g_off[3][NN];
__device__ int   g_bsum[3][128];
__device__ int   g_bsum2[3][128];
__device__ __align__(16) int2 g_epack[3][EE];   // (src, coef-as-int)

// ---------------- helpers ----------------------------------------------------
__device__ __forceinline__ void red_add_v4(float4* addr, float4 v) {
    asm volatile("red.global.add.v4.f32 [%0], {%1,%2,%3,%4};"
                 :: "l"(addr), "f"(v.x), "f"(v.y), "f"(v.z), "f"(v.w)
                 : "memory");
}
__device__ __forceinline__ void hacc4(float4& a0, float4& a1, float cf, const uint4& v) {
    float2 x0 = __half22float2(*reinterpret_cast<const __half2*>(&v.x));
    float2 x1 = __half22float2(*reinterpret_cast<const __half2*>(&v.y));
    float2 x2 = __half22float2(*reinterpret_cast<const __half2*>(&v.z));
    float2 x3 = __half22float2(*reinterpret_cast<const __half2*>(&v.w));
    a0.x = fmaf(cf, x0.x, a0.x); a0.y = fmaf(cf, x0.y, a0.y);
    a0.z = fmaf(cf, x1.x, a0.z); a0.w = fmaf(cf, x1.y, a0.w);
    a1.x = fmaf(cf, x2.x, a1.x); a1.y = fmaf(cf, x2.y, a1.y);
    a1.z = fmaf(cf, x3.x, a1.z); a1.w = fmaf(cf, x3.y, a1.w);
}
__device__ __forceinline__ void hacc2(float4& a, float cf, const uint2& v) {
    float2 x0 = __half22float2(*reinterpret_cast<const __half2*>(&v.x));
    float2 x1 = __half22float2(*reinterpret_cast<const __half2*>(&v.y));
    a.x = fmaf(cf, x0.x, a.x); a.y = fmaf(cf, x0.y, a.y);
    a.z = fmaf(cf, x1.x, a.z); a.w = fmaf(cf, x1.y, a.w);
}
__device__ __forceinline__ uint2 pack_half4(float4 v) {
    __half2 h0 = __float22half2_rn(make_float2(v.x, v.y));
    __half2 h1 = __float22half2_rn(make_float2(v.z, v.w));
    uint2 s;
    s.x = *reinterpret_cast<uint32_t*>(&h0);
    s.y = *reinterpret_cast<uint32_t*>(&h1);
    return s;
}
__device__ __forceinline__ float4 unpack_half4(uint2 s) {
    float2 a = __half22float2(*reinterpret_cast<const __half2*>(&s.x));
    float2 b = __half22float2(*reinterpret_cast<const __half2*>(&s.y));
    return make_float4(a.x, a.y, b.x, b.y);
}
__device__ __forceinline__ uint32_t hrelu2(uint32_t v) {
    __half2 h = *reinterpret_cast<__half2*>(&v);
    __half2 z = __float2half2_rn(0.f);
    h = __hmax2(h, z);
    return *reinterpret_cast<uint32_t*>(&h);
}
__device__ __forceinline__ void mma16816(float* c, const uint32_t* a, const uint32_t* b) {
    asm volatile(
        "mma.sync.aligned.m16n8k16.row.col.f32.f16.f16.f32 "
        "{%0,%1,%2,%3}, {%4,%5,%6,%7}, {%8,%9}, {%0,%1,%2,%3};"
        : "+f"(c[0]), "+f"(c[1]), "+f"(c[2]), "+f"(c[3])
        : "r"(a[0]), "r"(a[1]), "r"(a[2]), "r"(a[3]), "r"(b[0]), "r"(b[1]));
}

// ---------------- per-pass setup ---------------------------------------------
__global__ void zero_kernel(int p) {
    int i = blockIdx.x * blockDim.x + threadIdx.x;
    if (i < NN)      { g_deg[p][i] = 0; g_off[p][i] = 0; }
    if (i < GG * HH) g_psum[p][i] = 0.f;
    if (i < GG)      g_pcnt[p][i] = 0;
}

__global__ void deg_kernel(const int* __restrict__ dst, int p) {
    int e = blockIdx.x * blockDim.x + threadIdx.x;
    if (e < EE) atomicAdd(&g_deg[p][dst[e]], 1);
}

__global__ void dinv_kernel(int p) {
    int i = blockIdx.x * blockDim.x + threadIdx.x;
    if (i < NN) {
        float d = (float)g_deg[p][i] + 1.0f;
        g_dinv[p][i]  = rsqrtf(d);
        g_dinv2[p][i] = 1.0f / d;
    }
}

// x fp32 -> fp16
__global__ void xcvt_kernel(const float* __restrict__ x, __half* __restrict__ xh) {
    size_t i = ((size_t)blockIdx.x * blockDim.x + threadIdx.x) * 4;
    if (i >= (size_t)NN * FIN) return;
    float4 v = *reinterpret_cast<const float4*>(x + i);
    *reinterpret_cast<uint2*>(xh + i) = pack_half4(v);
}

// W [K][256] fp32 -> WT [256][K] fp16
__global__ void wt_kernel(const float* __restrict__ W, __half* __restrict__ WT, int K) {
    int idx = blockIdx.x * blockDim.x + threadIdx.x;
    if (idx >= 256 * K) return;
    int n = idx / K, k = idx % K;
    WT[idx] = __float2half(W[(size_t)k * 256 + n]);
}

// ---------------- exclusive scan of deg -> rowptr ------------------------------
__global__ void scan1_kernel(int p) {
    __shared__ int s[1024];
    int t = threadIdx.x;
    int i = blockIdx.x * 1024 + t;
    int v = (i < NN) ? g_deg[p][i] : 0;
    int x = v;
    s[t] = x;
    __syncthreads();
#pragma unroll
    for (int off = 1; off < 1024; off <<= 1) {
        int y = (t >= off) ? s[t - off] : 0;
        __syncthreads();
        x += y;
        s[t] = x;
        __syncthreads();
    }
    if (i < NN) g_rowptr[p][i] = x - v;
    if (t == 1023) g_bsum[p][blockIdx.x] = x;
}

__global__ void scan2_kernel(int p) {
    __shared__ int s[128];
    int t = threadIdx.x;
    const int NB = (NN + 1023) >> 10;
    int v = (t < NB) ? g_bsum[p][t] : 0;
    int x = v;
    s[t] = x;
    __syncthreads();
#pragma unroll
    for (int off = 1; off < 128; off <<= 1) {
        int y = (t >= off) ? s[t - off] : 0;
        __syncthreads();
        x += y;
        s[t] = x;
        __syncthreads();
    }
    g_bsum2[p][t] = x - v;
}

__global__ void scan3_kernel(int p) {
    int i = blockIdx.x * blockDim.x + threadIdx.x;
    if (i < NN) g_rowptr[p][i] += g_bsum2[p][i >> 10];
    if (i == 0) g_rowptr[p][NN] = EE;
}

__global__ void csr_kernel(const int* __restrict__ src, const int* __restrict__ dst, int p) {
    int e = blockIdx.x * blockDim.x + threadIdx.x;
    if (e >= EE) return;
    int s = src[e], d = dst[e];
    float coef = g_dinv[p][s] * g_dinv[p][d];
    int pos = g_rowptr[p][d] + atomicAdd(&g_off[p][d], 1);
    g_epack[p][pos] = make_int2(s, __float_as_int(coef));
}

__global__ void pcnt_kernel(const int* __restrict__ batch, int p) {
    int i = blockIdx.x * blockDim.x + threadIdx.x;
    if (i < NN) atomicAdd(&g_pcnt[p][batch[i]], 1);
}

// ---------------- layer-0 input aggregation: agg = Â x (fp16 in/out, MLP=8) ----
__global__ void __launch_bounds__(256)
pullx_kernel(const __half* __restrict__ xh, __half* __restrict__ agg, int p)
{
    int n = (int)((blockIdx.x * (unsigned)blockDim.x + threadIdx.x) >> 5);
    int lane = threadIdx.x & 31;
    if (n >= NN) return;
    int c = lane * 4;

    float d2 = g_dinv2[p][n];
    float4 sv = unpack_half4(*reinterpret_cast<const uint2*>(xh + (size_t)n * FIN + c));
    float4 acc = make_float4(sv.x * d2, sv.y * d2, sv.z * d2, sv.w * d2);

    int e = g_rowptr[p][n];
    int end = g_rowptr[p][n + 1];
    const int2* ep = g_epack[p];

    for (; e + 7 < end; e += 8) {
        int2 pe[8];
        uint2 v[8];
#pragma unroll
        for (int j = 0; j < 8; j++) pe[j] = ep[e + j];
#pragma unroll
        for (int j = 0; j < 8; j++)
            v[j] = *reinterpret_cast<const uint2*>(xh + (size_t)pe[j].x * FIN + c);
#pragma unroll
        for (int j = 0; j < 8; j++)
            hacc2(acc, __int_as_float(pe[j].y), v[j]);
    }
    for (; e < end; e++) {
        int2 pe = ep[e];
        uint2 v = *reinterpret_cast<const uint2*>(xh + (size_t)pe.x * FIN + c);
        hacc2(acc, __int_as_float(pe.y), v);
    }

    *reinterpret_cast<uint2*>(agg + (size_t)n * FIN + c) = pack_half4(acc);
}

// ---------------- GEMM via HMMA (mma.sync m16n8k16) ---------------------------
// out = act(A) @ W (+bias).  A fp16 [NN][K], WT fp16 [256][K], out fp16.
// Block: 128x128 tile, 256 threads = 8 warps (4 m-slices x 2 n-slices).
// smem layout: [kpair][row], stride 136 words -> conflict-free fragment loads.
template <int K, bool RELU, bool BIAS>
__global__ void __launch_bounds__(256, 2)
gemmh_kernel(const __half* __restrict__ A, const __half* __restrict__ WT,
             const float* __restrict__ bias, __half* __restrict__ Hout)
{
    __shared__ uint32_t As2[16 * 136];
    __shared__ uint32_t Bs2[16 * 136];

    const int t = threadIdx.x;
    const int lane = t & 31;
    const int wid = t >> 5;
    const int g = lane >> 2;      // groupID 0..7
    const int q = lane & 3;       // thread-in-group 0..3
    const int wm = wid & 3;       // 32-row slice
    const int wn = wid >> 2;      // 64-col slice
    const int rowBase = blockIdx.x * 128;
    const int colBase = blockIdx.y * 128;

    const int sr = t >> 1;        // staging row 0..127
    const int sh = t & 1;         // staging k-half (16 halves each)

    float acc[2][8][4];
#pragma unroll
    for (int mt = 0; mt < 2; mt++)
#pragma unroll
        for (int nt = 0; nt < 8; nt++)
#pragma unroll
            for (int i = 0; i < 4; i++) acc[mt][nt][i] = 0.f;

    const int arow = rowBase + sr;
    uint4 pa0, pa1, pb0, pb1;
    {
        pa0 = make_uint4(0u,0u,0u,0u); pa1 = pa0;
        if (arow < NN) {
            const __half* ap = A + (size_t)arow * K + sh * 16;
            pa0 = *reinterpret_cast<const uint4*>(ap);
            pa1 = *reinterpret_cast<const uint4*>(ap + 8);
        }
        const __half* bp = WT + (size_t)(colBase + sr) * K + sh * 16;
        pb0 = *reinterpret_cast<const uint4*>(bp);
        pb1 = *reinterpret_cast<const uint4*>(bp + 8);
    }

    for (int kb = 0; kb < K; kb += 32) {
        // ---- store staged chunk to smem ----
        {
            uint32_t av[8] = {pa0.x, pa0.y, pa0.z, pa0.w, pa1.x, pa1.y, pa1.z, pa1.w};
            uint32_t bv[8] = {pb0.x, pb0.y, pb0.z, pb0.w, pb1.x, pb1.y, pb1.z, pb1.w};
            if (RELU) {
#pragma unroll
                for (int j = 0; j < 8; j++) av[j] = hrelu2(av[j]);
            }
            int kp0 = sh * 8;
#pragma unroll
            for (int j = 0; j < 8; j++) {
                As2[(kp0 + j) * 136 + sr] = av[j];
                Bs2[(kp0 + j) * 136 + sr] = bv[j];
            }
        }
        __syncthreads();

        // ---- prefetch next chunk ----
        if (kb + 32 < K) {
            int kn = kb + 32;
            pa0 = make_uint4(0u,0u,0u,0u); pa1 = pa0;
            if (arow < NN) {
                const __half* ap = A + (size_t)arow * K + kn + sh * 16;
                pa0 = *reinterpret_cast<const uint4*>(ap);
                pa1 = *reinterpret_cast<const uint4*>(ap + 8);
            }
            const __half* bp = WT + (size_t)(colBase + sr) * K + kn + sh * 16;
            pb0 = *reinterpret_cast<const uint4*>(bp);
            pb1 = *reinterpret_cast<const uint4*>(bp + 8);
        }

        // ---- compute: two k16 steps ----
#pragma unroll
        for (int s = 0; s < 2; s++) {
            int kp = s * 8 + q;
            uint32_t afr[2][4];
#pragma unroll
            for (int mt = 0; mt < 2; mt++) {
                int R = wm * 32 + mt * 16;
                afr[mt][0] = As2[kp * 136 + R + g];
                afr[mt][1] = As2[kp * 136 + R + 8 + g];
                afr[mt][2] = As2[(kp + 4) * 136 + R + g];
                afr[mt][3] = As2[(kp + 4) * 136 + R + 8 + g];
            }
            uint32_t bfr[8][2];
#pragma unroll
            for (int nt = 0; nt < 8; nt++) {
                int nc = wn * 64 + nt * 8 + g;
                bfr[nt][0] = Bs2[kp * 136 + nc];
                bfr[nt][1] = Bs2[(kp + 4) * 136 + nc];
            }
#pragma unroll
            for (int mt = 0; mt < 2; mt++)
#pragma unroll
                for (int nt = 0; nt < 8; nt++)
                    mma16816(acc[mt][nt], afr[mt], bfr[nt]);
        }
        __syncthreads();
    }

    // ---- epilogue ----
#pragma unroll
    for (int mt = 0; mt < 2; mt++) {
        int row0 = rowBase + wm * 32 + mt * 16 + g;
        int row1 = row0 + 8;
#pragma unroll
        for (int nt = 0; nt < 8; nt++) {
            int col = colBase + wn * 64 + nt * 8 + q * 2;
            float bx = 0.f, by = 0.f;
            if (BIAS) {
                float2 bb = *reinterpret_cast<const float2*>(bias + col);
                bx = bb.x; by = bb.y;
            }
            if (row0 < NN) {
                __half2 h = __float22half2_rn(make_float2(acc[mt][nt][0] + bx,
                                                          acc[mt][nt][1] + by));
                *reinterpret_cast<uint32_t*>(Hout + (size_t)row0 * HH + col) =
                    *reinterpret_cast<uint32_t*>(&h);
            }
            if (row1 < NN) {
                __half2 h = __float22half2_rn(make_float2(acc[mt][nt][2] + bx,
                                                          acc[mt][nt][3] + by));
                *reinterpret_cast<uint32_t*>(Hout + (size_t)row1 * HH + col) =
                    *reinterpret_cast<uint32_t*>(&h);
            }
        }
    }
}

// ---------------- pull aggregation (fp16 in/out, 256 cols/warp, MLP=8) ---------
__global__ void __launch_bounds__(256)
pull_kernel(const float* __restrict__ bias, const __half* __restrict__ h,
            __half* __restrict__ out, const int* __restrict__ batch,
            int doPool, int p)
{
    int n = (int)((blockIdx.x * (unsigned)blockDim.x + threadIdx.x) >> 5);
    int lane = threadIdx.x & 31;
    if (n >= NN) return;
    int c = lane * 8;

    float d2 = g_dinv2[p][n];
    float4 ba = *reinterpret_cast<const float4*>(bias + c);
    float4 bb = *reinterpret_cast<const float4*>(bias + c + 4);
    float4 accA = ba, accB = bb;
    {
        uint4 sv = *reinterpret_cast<const uint4*>(h + (size_t)n * HH + c);
        hacc4(accA, accB, d2, sv);
    }

    int e = g_rowptr[p][n];
    int end = g_rowptr[p][n + 1];
    const int2* ep = g_epack[p];

    for (; e + 7 < end; e += 8) {
        int2 pe[8];
        uint4 v[8];
#pragma unroll
        for (int j = 0; j < 8; j++) pe[j] = ep[e + j];
#pragma unroll
        for (int j = 0; j < 8; j++)
            v[j] = *reinterpret_cast<const uint4*>(h + (size_t)pe[j].x * HH + c);
#pragma unroll
        for (int j = 0; j < 8; j++)
            hacc4(accA, accB, __int_as_float(pe[j].y), v[j]);
    }
    for (; e < end; e++) {
        int2 pe = ep[e];
        uint4 v = *reinterpret_cast<const uint4*>(h + (size_t)pe.x * HH + c);
        hacc4(accA, accB, __int_as_float(pe.y), v);
    }

    if (!doPool) {
        uint4 s;
        uint2 sa = pack_half4(accA), sb = pack_half4(accB);
        s.x = sa.x; s.y = sa.y; s.z = sb.x; s.w = sb.y;
        *reinterpret_cast<uint4*>(out + (size_t)n * HH + c) = s;
    } else {
        int g = __ldg(&batch[n]);
        red_add_v4(reinterpret_cast<float4*>(g_psum[p] + g * HH + c), accA);
        red_add_v4(reinterpret_cast<float4*>(g_psum[p] + g * HH + c + 4), accB);
    }
}

// ---------------- z = mean @ lin0_W + lin0_b -----------------------------------
__global__ void __launch_bounds__(128)
z_kernel(const float* __restrict__ lin0W, const float* __restrict__ lin0b,
         float* __restrict__ outz, int p)
{
    __shared__ float mean[HH];
    int g = blockIdx.x;
    int t = threadIdx.x;
    float c = fmaxf((float)g_pcnt[p][g], 1.0f);
    mean[t]       = g_psum[p][g * HH + t] / c;
    mean[t + 128] = g_psum[p][g * HH + t + 128] / c;
    __syncthreads();
    float acc = lin0b[t];
#pragma unroll 8
    for (int k = 0; k < HH; k++)
        acc = fmaf(mean[k], __ldg(&lin0W[(size_t)k * HO + t]), acc);
    outz[g * HO + t] = acc;
}

// ---------------- triplet head ------------------------------------------------
__global__ void final_kernel(const float* __restrict__ linW,
                             const float* __restrict__ linb,
                             float* __restrict__ out)
{
    __shared__ int s1, s2;
    int g = threadIdx.x;
    if (g == 0) { s1 = 0; s2 = 0; }
    __syncthreads();

    const float* z0 = out;
    const float* z1 = out + GG * HO;
    const float* z2 = out + 2 * GG * HO;
    const float EPS = 1e-6f;

    float dp = 0.f, dn = 0.f;
    float y1 = linb[0], y2 = linb[0];
#pragma unroll 4
    for (int j = 0; j < HO; j++) {
        float a = z0[g * HO + j];
        float b = z1[g * HO + j];
        float c = z2[g * HO + j];
        float e1 = a - b + EPS; dp = fmaf(e1, e1, dp);
        float e2 = a - c + EPS; dn = fmaf(e2, e2, dn);
        float wa = linW[j], wb = linW[HO + j];
        y1 = fmaf(a, wa, fmaf(b, wb, y1));
        y2 = fmaf(a, wa, fmaf(c, wb, y2));
    }
    dp = sqrtf(dp); dn = sqrtf(dn);
    float sp = 1.0f / (1.0f + expf(-y1));
    float sn = 1.0f / (1.0f + expf(-y2));

    const int base = 3 * GG * HO;
    out[base + 1 + g] = sp;
    out[base + 1 + GG + g] = sn;
    if (dn - dp > 0.f) atomicAdd(&s1, 1);
    if (sp - sn > 0.f) atomicAdd(&s2, 1);
    __syncthreads();
    if (g == 0) {
        out[base] = (float)s1;
        out[base + 1 + 2 * GG] = (float)s2;
    }
}

// ---------------- host orchestration ------------------------------------------
extern "C" void kernel_launch(void* const* d_in, const int* in_sizes, int n_in,
                              void* d_out, int out_size)
{
    const float* x[3]     = { (const float*)d_in[0], (const float*)d_in[1], (const float*)d_in[2] };
    const int*   ei[3]    = { (const int*)d_in[3], (const int*)d_in[4], (const int*)d_in[5] };
    const int*   batch[3] = { (const int*)d_in[6], (const int*)d_in[7], (const int*)d_in[8] };
    const float* W0 = (const float*)d_in[9];
    const float* b0 = (const float*)d_in[10];
    const float* W1 = (const float*)d_in[11];
    const float* b1 = (const float*)d_in[12];
    const float* W2 = (const float*)d_in[13];
    const float* b2 = (const float*)d_in[14];
    const float* lin0W = (const float*)d_in[15];
    const float* lin0b = (const float*)d_in[16];
    const float* linW  = (const float*)d_in[17];
    const float* linb  = (const float*)d_in[18];
    float* out = (float*)d_out;

    static cudaStream_t st[3];
    static cudaEvent_t evRoot, evDone[3];
    static bool inited = false;
    if (!inited) {
        for (int i = 0; i < 3; i++) cudaStreamCreateWithFlags(&st[i], cudaStreamNonBlocking);
        cudaEventCreateWithFlags(&evRoot, cudaEventDisableTiming);
        for (int i = 0; i < 3; i++) cudaEventCreateWithFlags(&evDone[i], cudaEventDisableTiming);
        inited = true;
    }

    __half *hhptr[3], *aptr[3], *xhptr[3], *aggptr[3], *wtbase;
    {
        __half* hb;
        cudaGetSymbolAddress((void**)&hb, g_hh);
        for (int i = 0; i < 3; i++) hhptr[i] = hb + (size_t)i * NH;
        cudaGetSymbolAddress((void**)&hb, g_a);
        for (int i = 0; i < 3; i++) aptr[i] = hb + (size_t)i * NH;
        cudaGetSymbolAddress((void**)&hb, g_xh);
        for (int i = 0; i < 3; i++) xhptr[i] = hb + (size_t)i * NN * FIN;
        cudaGetSymbolAddress((void**)&hb, g_agg);
        for (int i = 0; i < 3; i++) aggptr[i] = hb + (size_t)i * NN * FIN;
        cudaGetSymbolAddress((void**)&wtbase, g_wt);
    }
    __half* wt1 = wtbase;                       // [256][256]
    __half* wt2 = wtbase + 256 * HH;            // [256][256]
    __half* wt0 = wtbase + 256 * HH * 2;        // [256][128]

    dim3 gemmGrid((NN + 127) / 128, HH / 128);
    int  warpBlocks = (int)(((long long)NN * 32 + 255) / 256);
    const int NB = (NN + 1023) / 1024;
    int  xcvtBlocks = (int)(((size_t)NN * FIN / 4 + 255) / 256);

    // weight transposes (shared by all passes) on the capture stream
    wt_kernel<<<(256 * HH + 255) / 256, 256>>>(W1, wt1, HH);
    wt_kernel<<<(256 * HH + 255) / 256, 256>>>(W2, wt2, HH);
    wt_kernel<<<(256 * FIN + 255) / 256, 256>>>(W0, wt0, FIN);

    cudaEventRecord(evRoot, 0);

    for (int p = 0; p < 3; p++) {
        cudaStream_t s = st[p];
        cudaStreamWaitEvent(s, evRoot, 0);

        const int* srcp = ei[p];
        const int* dstp = ei[p] + EE;

        // ---- per-pass graph prep + x conversion ----
        zero_kernel<<<(NN + 255) / 256, 256, 0, s>>>(p);
        xcvt_kernel<<<xcvtBlocks, 256, 0, s>>>(x[p], xhptr[p]);
        deg_kernel<<<(EE + 255) / 256, 256, 0, s>>>(dstp, p);
        dinv_kernel<<<(NN + 255) / 256, 256, 0, s>>>(p);
        scan1_kernel<<<NB, 1024, 0, s>>>(p);
        scan2_kernel<<<1, 128, 0, s>>>(p);
        scan3_kernel<<<(NN + 255) / 256, 256, 0, s>>>(p);
        csr_kernel<<<(EE + 255) / 256, 256, 0, s>>>(srcp, dstp, p);
        pcnt_kernel<<<(NN + 255) / 256, 256, 0, s>>>(batch[p], p);

        // ---- layer 0: agg = Â x (fp16) ; a = agg @ W0 + b0 (fp16)
        pullx_kernel<<<warpBlocks, 256, 0, s>>>(xhptr[p], aggptr[p], p);
        gemmh_kernel<FIN, false, true><<<gemmGrid, 256, 0, s>>>(aggptr[p], wt0, b0, aptr[p]);

        // ---- layer 1: hh = relu(a) @ W1 ; pull+b1 -> a (fp16)
        gemmh_kernel<HH, true, false><<<gemmGrid, 256, 0, s>>>(aptr[p], wt1, nullptr, hhptr[p]);
        pull_kernel<<<warpBlocks, 256, 0, s>>>(b1, hhptr[p], aptr[p], nullptr, 0, p);

        // ---- layer 2: hh = relu(a) @ W2 ; pull+b2 -> pooled psum
        gemmh_kernel<HH, true, false><<<gemmGrid, 256, 0, s>>>(aptr[p], wt2, nullptr, hhptr[p]);
        pull_kernel<<<warpBlocks, 256, 0, s>>>(b2, hhptr[p], nullptr, batch[p], 1, p);

        // ---- z_p = mean @ lin0_W + lin0_b
        z_kernel<<<GG, 128, 0, s>>>(lin0W, lin0b, out + (size_t)p * GG * HO, p);

        cudaEventRecord(evDone[p], s);
    }

    for (int p = 0; p < 3; p++) cudaStreamWaitEvent(0, evDone[p], 0);

    final_kernel<<<1, GG>>>(linW, linb, out);
}

// round 12
// speedup vs baseline: 1.7663x; 1.0917x over previous
#include <cuda_runtime.h>
#include <cuda_bf16.h>
#include <cuda_fp16.h>
#include <stdint.h>
#include <math.h>

// Problem constants (fixed by the dataset)
#define NN 100000
#define EE 3200000
#define FIN 128
#define HH  256
#define GG  64
#define HO  128   // H/2

typedef unsigned long long u64;

// ---------------- per-pass scratch (static device globals) --------------------
#define NH ((size_t)NN * HH)
__device__ __align__(16) __half g_a  [3][NH];                 // GEMM out (gather source)
__device__ __align__(16) __half g_agg[3][NH];                 // pull out (GEMM A input)
__device__ __align__(16) __half g_xh [3][(size_t)NN * FIN];   // fp16 x
__device__ __align__(16) __half g_wt [256 * HH + 256 * FIN];  // fp16 WT: W1 [256][256], W0 [256][128]
__device__ float g_dinv [3][NN];
__device__ float g_dinv2[3][NN];
__device__ int   g_deg  [3][NN];
__device__ __align__(16) float g_psum[3][GG * HH];
__device__ int   g_pcnt[3][GG];
__device__ int   g_rowptr[3][NN + 1];
__device__ int   g_off[3][NN];
__device__ int   g_bsum[3][128];
__device__ int   g_bsum2[3][128];
__device__ __align__(16) int2 g_epack[3][EE];   // (src, coef-as-int)

// ---------------- helpers ----------------------------------------------------
__device__ __forceinline__ void red_add_v4(float4* addr, float4 v) {
    asm volatile("red.global.add.v4.f32 [%0], {%1,%2,%3,%4};"
                 :: "l"(addr), "f"(v.x), "f"(v.y), "f"(v.z), "f"(v.w)
                 : "memory");
}
__device__ __forceinline__ uint32_t hrelu2(uint32_t v) {
    __half2 h = *reinterpret_cast<__half2*>(&v);
    __half2 z = __float2half2_rn(0.f);
    h = __hmax2(h, z);
    return *reinterpret_cast<uint32_t*>(&h);
}
__device__ __forceinline__ void hacc4(float4& a0, float4& a1, float cf, uint4 v, bool relu) {
    if (relu) { v.x = hrelu2(v.x); v.y = hrelu2(v.y); v.z = hrelu2(v.z); v.w = hrelu2(v.w); }
    float2 x0 = __half22float2(*reinterpret_cast<const __half2*>(&v.x));
    float2 x1 = __half22float2(*reinterpret_cast<const __half2*>(&v.y));
    float2 x2 = __half22float2(*reinterpret_cast<const __half2*>(&v.z));
    float2 x3 = __half22float2(*reinterpret_cast<const __half2*>(&v.w));
    a0.x = fmaf(cf, x0.x, a0.x); a0.y = fmaf(cf, x0.y, a0.y);
    a0.z = fmaf(cf, x1.x, a0.z); a0.w = fmaf(cf, x1.y, a0.w);
    a1.x = fmaf(cf, x2.x, a1.x); a1.y = fmaf(cf, x2.y, a1.y);
    a1.z = fmaf(cf, x3.x, a1.z); a1.w = fmaf(cf, x3.y, a1.w);
}
__device__ __forceinline__ void hacc2(float4& a, float cf, const uint2& v) {
    float2 x0 = __half22float2(*reinterpret_cast<const __half2*>(&v.x));
    float2 x1 = __half22float2(*reinterpret_cast<const __half2*>(&v.y));
    a.x = fmaf(cf, x0.x, a.x); a.y = fmaf(cf, x0.y, a.y);
    a.z = fmaf(cf, x1.x, a.z); a.w = fmaf(cf, x1.y, a.w);
}
__device__ __forceinline__ uint2 pack_half4(float4 v) {
    __half2 h0 = __float22half2_rn(make_float2(v.x, v.y));
    __half2 h1 = __float22half2_rn(make_float2(v.z, v.w));
    uint2 s;
    s.x = *reinterpret_cast<uint32_t*>(&h0);
    s.y = *reinterpret_cast<uint32_t*>(&h1);
    return s;
}
__device__ __forceinline__ float4 unpack_half4(uint2 s) {
    float2 a = __half22float2(*reinterpret_cast<const __half2*>(&s.x));
    float2 b = __half22float2(*reinterpret_cast<const __half2*>(&s.y));
    return make_float4(a.x, a.y, b.x, b.y);
}
__device__ __forceinline__ void mma16816(float* c, const uint32_t* a, const uint32_t* b) {
    asm volatile(
        "mma.sync.aligned.m16n8k16.row.col.f32.f16.f16.f32 "
        "{%0,%1,%2,%3}, {%4,%5,%6,%7}, {%8,%9}, {%0,%1,%2,%3};"
        : "+f"(c[0]), "+f"(c[1]), "+f"(c[2]), "+f"(c[3])
        : "r"(a[0]), "r"(a[1]), "r"(a[2]), "r"(a[3]), "r"(b[0]), "r"(b[1]));
}

// ---------------- per-pass setup ---------------------------------------------
__global__ void zero_kernel(int p) {
    int i = blockIdx.x * blockDim.x + threadIdx.x;
    if (i < NN)      { g_deg[p][i] = 0; g_off[p][i] = 0; }
    if (i < GG * HH) g_psum[p][i] = 0.f;
    if (i < GG)      g_pcnt[p][i] = 0;
}

__global__ void deg_kernel(const int* __restrict__ dst, int p) {
    int e = blockIdx.x * blockDim.x + threadIdx.x;
    if (e < EE) atomicAdd(&g_deg[p][dst[e]], 1);
}

__global__ void dinv_kernel(int p) {
    int i = blockIdx.x * blockDim.x + threadIdx.x;
    if (i < NN) {
        float d = (float)g_deg[p][i] + 1.0f;
        g_dinv[p][i]  = rsqrtf(d);
        g_dinv2[p][i] = 1.0f / d;
    }
}

// x fp32 -> fp16
__global__ void xcvt_kernel(const float* __restrict__ x, __half* __restrict__ xh) {
    size_t i = ((size_t)blockIdx.x * blockDim.x + threadIdx.x) * 4;
    if (i >= (size_t)NN * FIN) return;
    float4 v = *reinterpret_cast<const float4*>(x + i);
    *reinterpret_cast<uint2*>(xh + i) = pack_half4(v);
}

// W [K][256] fp32 -> WT [256][K] fp16
__global__ void wt_kernel(const float* __restrict__ W, __half* __restrict__ WT, int K) {
    int idx = blockIdx.x * blockDim.x + threadIdx.x;
    if (idx >= 256 * K) return;
    int n = idx / K, k = idx % K;
    WT[idx] = __float2half(W[(size_t)k * 256 + n]);
}

// ---------------- exclusive scan of deg -> rowptr ------------------------------
__global__ void scan1_kernel(int p) {
    __shared__ int s[1024];
    int t = threadIdx.x;
    int i = blockIdx.x * 1024 + t;
    int v = (i < NN) ? g_deg[p][i] : 0;
    int x = v;
    s[t] = x;
    __syncthreads();
#pragma unroll
    for (int off = 1; off < 1024; off <<= 1) {
        int y = (t >= off) ? s[t - off] : 0;
        __syncthreads();
        x += y;
        s[t] = x;
        __syncthreads();
    }
    if (i < NN) g_rowptr[p][i] = x - v;
    if (t == 1023) g_bsum[p][blockIdx.x] = x;
}

__global__ void scan2_kernel(int p) {
    __shared__ int s[128];
    int t = threadIdx.x;
    const int NB = (NN + 1023) >> 10;
    int v = (t < NB) ? g_bsum[p][t] : 0;
    int x = v;
    s[t] = x;
    __syncthreads();
#pragma unroll
    for (int off = 1; off < 128; off <<= 1) {
        int y = (t >= off) ? s[t - off] : 0;
        __syncthreads();
        x += y;
        s[t] = x;
        __syncthreads();
    }
    g_bsum2[p][t] = x - v;
}

__global__ void scan3_kernel(int p) {
    int i = blockIdx.x * blockDim.x + threadIdx.x;
    if (i < NN) g_rowptr[p][i] += g_bsum2[p][i >> 10];
    if (i == 0) g_rowptr[p][NN] = EE;
}

__global__ void csr_kernel(const int* __restrict__ src, const int* __restrict__ dst, int p) {
    int e = blockIdx.x * blockDim.x + threadIdx.x;
    if (e >= EE) return;
    int s = src[e], d = dst[e];
    float coef = g_dinv[p][s] * g_dinv[p][d];
    int pos = g_rowptr[p][d] + atomicAdd(&g_off[p][d], 1);
    g_epack[p][pos] = make_int2(s, __float_as_int(coef));
}

__global__ void pcnt_kernel(const int* __restrict__ batch, int p) {
    int i = blockIdx.x * blockDim.x + threadIdx.x;
    if (i < NN) atomicAdd(&g_pcnt[p][batch[i]], 1);
}

// ---------------- layer-0 input aggregation: agg = Â x (fp16 in/out, MLP=8) ----
__global__ void __launch_bounds__(256)
pullx_kernel(const __half* __restrict__ xh, __half* __restrict__ agg, int p)
{
    int n = (int)((blockIdx.x * (unsigned)blockDim.x + threadIdx.x) >> 5);
    int lane = threadIdx.x & 31;
    if (n >= NN) return;
    int c = lane * 4;

    float d2 = g_dinv2[p][n];
    float4 sv = unpack_half4(*reinterpret_cast<const uint2*>(xh + (size_t)n * FIN + c));
    float4 acc = make_float4(sv.x * d2, sv.y * d2, sv.z * d2, sv.w * d2);

    int e = g_rowptr[p][n];
    int end = g_rowptr[p][n + 1];
    const int2* ep = g_epack[p];

    for (; e + 7 < end; e += 8) {
        int2 pe[8];
        uint2 v[8];
#pragma unroll
        for (int j = 0; j < 8; j++) pe[j] = ep[e + j];
#pragma unroll
        for (int j = 0; j < 8; j++)
            v[j] = *reinterpret_cast<const uint2*>(xh + (size_t)pe[j].x * FIN + c);
#pragma unroll
        for (int j = 0; j < 8; j++)
            hacc2(acc, __int_as_float(pe[j].y), v[j]);
    }
    for (; e < end; e++) {
        int2 pe = ep[e];
        uint2 v = *reinterpret_cast<const uint2*>(xh + (size_t)pe.x * FIN + c);
        hacc2(acc, __int_as_float(pe.y), v);
    }

    *reinterpret_cast<uint2*>(agg + (size_t)n * FIN + c) = pack_half4(acc);
}

// ---------------- GEMM via HMMA: out = A @ W + bias (A fp16, out fp16) --------
template <int K>
__global__ void __launch_bounds__(256, 2)
gemmh_kernel(const __half* __restrict__ A, const __half* __restrict__ WT,
             const float* __restrict__ bias, __half* __restrict__ Hout)
{
    __shared__ uint32_t As2[16 * 136];
    __shared__ uint32_t Bs2[16 * 136];

    const int t = threadIdx.x;
    const int lane = t & 31;
    const int wid = t >> 5;
    const int g = lane >> 2;
    const int q = lane & 3;
    const int wm = wid & 3;
    const int wn = wid >> 2;
    const int rowBase = blockIdx.x * 128;
    const int colBase = blockIdx.y * 128;

    const int sr = t >> 1;
    const int sh = t & 1;

    float acc[2][8][4];
#pragma unroll
    for (int mt = 0; mt < 2; mt++)
#pragma unroll
        for (int nt = 0; nt < 8; nt++)
#pragma unroll
            for (int i = 0; i < 4; i++) acc[mt][nt][i] = 0.f;

    const int arow = rowBase + sr;
    uint4 pa0, pa1, pb0, pb1;
    {
        pa0 = make_uint4(0u,0u,0u,0u); pa1 = pa0;
        if (arow < NN) {
            const __half* ap = A + (size_t)arow * K + sh * 16;
            pa0 = *reinterpret_cast<const uint4*>(ap);
            pa1 = *reinterpret_cast<const uint4*>(ap + 8);
        }
        const __half* bp = WT + (size_t)(colBase + sr) * K + sh * 16;
        pb0 = *reinterpret_cast<const uint4*>(bp);
        pb1 = *reinterpret_cast<const uint4*>(bp + 8);
    }

    for (int kb = 0; kb < K; kb += 32) {
        {
            uint32_t av[8] = {pa0.x, pa0.y, pa0.z, pa0.w, pa1.x, pa1.y, pa1.z, pa1.w};
            uint32_t bv[8] = {pb0.x, pb0.y, pb0.z, pb0.w, pb1.x, pb1.y, pb1.z, pb1.w};
            int kp0 = sh * 8;
#pragma unroll
            for (int j = 0; j < 8; j++) {
                As2[(kp0 + j) * 136 + sr] = av[j];
                Bs2[(kp0 + j) * 136 + sr] = bv[j];
            }
        }
        __syncthreads();

        if (kb + 32 < K) {
            int kn = kb + 32;
            pa0 = make_uint4(0u,0u,0u,0u); pa1 = pa0;
            if (arow < NN) {
                const __half* ap = A + (size_t)arow * K + kn + sh * 16;
                pa0 = *reinterpret_cast<const uint4*>(ap);
                pa1 = *reinterpret_cast<const uint4*>(ap + 8);
            }
            const __half* bp = WT + (size_t)(colBase + sr) * K + kn + sh * 16;
            pb0 = *reinterpret_cast<const uint4*>(bp);
            pb1 = *reinterpret_cast<const uint4*>(bp + 8);
        }

#pragma unroll
        for (int s = 0; s < 2; s++) {
            int kp = s * 8 + q;
            uint32_t afr[2][4];
#pragma unroll
            for (int mt = 0; mt < 2; mt++) {
                int R = wm * 32 + mt * 16;
                afr[mt][0] = As2[kp * 136 + R + g];
                afr[mt][1] = As2[kp * 136 + R + 8 + g];
                afr[mt][2] = As2[(kp + 4) * 136 + R + g];
                afr[mt][3] = As2[(kp + 4) * 136 + R + 8 + g];
            }
            uint32_t bfr[8][2];
#pragma unroll
            for (int nt = 0; nt < 8; nt++) {
                int nc = wn * 64 + nt * 8 + g;
                bfr[nt][0] = Bs2[kp * 136 + nc];
                bfr[nt][1] = Bs2[(kp + 4) * 136 + nc];
            }
#pragma unroll
            for (int mt = 0; mt < 2; mt++)
#pragma unroll
                for (int nt = 0; nt < 8; nt++)
                    mma16816(acc[mt][nt], afr[mt], bfr[nt]);
        }
        __syncthreads();
    }

#pragma unroll
    for (int mt = 0; mt < 2; mt++) {
        int row0 = rowBase + wm * 32 + mt * 16 + g;
        int row1 = row0 + 8;
#pragma unroll
        for (int nt = 0; nt < 8; nt++) {
            int col = colBase + wn * 64 + nt * 8 + q * 2;
            float2 bb = *reinterpret_cast<const float2*>(bias + col);
            if (row0 < NN) {
                __half2 h = __float22half2_rn(make_float2(acc[mt][nt][0] + bb.x,
                                                          acc[mt][nt][1] + bb.y));
                *reinterpret_cast<uint32_t*>(Hout + (size_t)row0 * HH + col) =
                    *reinterpret_cast<uint32_t*>(&h);
            }
            if (row1 < NN) {
                __half2 h = __float22half2_rn(make_float2(acc[mt][nt][2] + bb.x,
                                                          acc[mt][nt][3] + bb.y));
                *reinterpret_cast<uint32_t*>(Hout + (size_t)row1 * HH + col) =
                    *reinterpret_cast<uint32_t*>(&h);
            }
        }
    }
}

// ---------------- pull: agg[n] = dinv2*relu(a[n]) + sum coef*relu(a[src]) ------
// doPool==1: pooled directly into psum (no node-output store).
__global__ void __launch_bounds__(256)
pull_kernel(const __half* __restrict__ a, __half* __restrict__ agg,
            const int* __restrict__ batch, int doPool, int p)
{
    int n = (int)((blockIdx.x * (unsigned)blockDim.x + threadIdx.x) >> 5);
    int lane = threadIdx.x & 31;
    if (n >= NN) return;
    int c = lane * 8;

    float d2 = g_dinv2[p][n];
    float4 accA = make_float4(0.f, 0.f, 0.f, 0.f);
    float4 accB = accA;
    {
        uint4 sv = *reinterpret_cast<const uint4*>(a + (size_t)n * HH + c);
        hacc4(accA, accB, d2, sv, true);
    }

    int e = g_rowptr[p][n];
    int end = g_rowptr[p][n + 1];
    const int2* ep = g_epack[p];

    for (; e + 7 < end; e += 8) {
        int2 pe[8];
        uint4 v[8];
#pragma unroll
        for (int j = 0; j < 8; j++) pe[j] = ep[e + j];
#pragma unroll
        for (int j = 0; j < 8; j++)
            v[j] = *reinterpret_cast<const uint4*>(a + (size_t)pe[j].x * HH + c);
#pragma unroll
        for (int j = 0; j < 8; j++)
            hacc4(accA, accB, __int_as_float(pe[j].y), v[j], true);
    }
    for (; e < end; e++) {
        int2 pe = ep[e];
        uint4 v = *reinterpret_cast<const uint4*>(a + (size_t)pe.x * HH + c);
        hacc4(accA, accB, __int_as_float(pe.y), v, true);
    }

    if (!doPool) {
        uint4 s;
        uint2 sa = pack_half4(accA), sb = pack_half4(accB);
        s.x = sa.x; s.y = sa.y; s.z = sb.x; s.w = sb.y;
        *reinterpret_cast<uint4*>(agg + (size_t)n * HH + c) = s;
    } else {
        int g = __ldg(&batch[n]);
        red_add_v4(reinterpret_cast<float4*>(g_psum[p] + g * HH + c), accA);
        red_add_v4(reinterpret_cast<float4*>(g_psum[p] + g * HH + c + 4), accB);
    }
}

// ---------------- z: mean = psum/cnt ; t2 = mean@W2 + b2 ; z = t2@lin0W + lin0b -
__global__ void __launch_bounds__(256)
z_kernel(const float* __restrict__ W2, const float* __restrict__ b2,
         const float* __restrict__ lin0W, const float* __restrict__ lin0b,
         float* __restrict__ outz, int p)
{
    __shared__ float mean[HH];
    __shared__ float t2[HH];
    int g = blockIdx.x;
    int t = threadIdx.x;   // 0..255
    float cnt = fmaxf((float)g_pcnt[p][g], 1.0f);
    mean[t] = g_psum[p][g * HH + t] / cnt;
    __syncthreads();

    // t2[t] = b2[t] + sum_k mean[k] * W2[k][t]
    float acc = b2[t];
#pragma unroll 8
    for (int k = 0; k < HH; k++)
        acc = fmaf(mean[k], __ldg(&W2[(size_t)k * HH + t]), acc);
    t2[t] = acc;
    __syncthreads();

    if (t < HO) {
        float z = lin0b[t];
#pragma unroll 8
        for (int k = 0; k < HH; k++)
            z = fmaf(t2[k], __ldg(&lin0W[(size_t)k * HO + t]), z);
        outz[g * HO + t] = z;
    }
}

// ---------------- triplet head ------------------------------------------------
__global__ void final_kernel(const float* __restrict__ linW,
                             const float* __restrict__ linb,
                             float* __restrict__ out)
{
    __shared__ int s1, s2;
    int g = threadIdx.x;
    if (g == 0) { s1 = 0; s2 = 0; }
    __syncthreads();

    const float* z0 = out;
    const float* z1 = out + GG * HO;
    const float* z2 = out + 2 * GG * HO;
    const float EPS = 1e-6f;

    float dp = 0.f, dn = 0.f;
    float y1 = linb[0], y2 = linb[0];
#pragma unroll 4
    for (int j = 0; j < HO; j++) {
        float a = z0[g * HO + j];
        float b = z1[g * HO + j];
        float c = z2[g * HO + j];
        float e1 = a - b + EPS; dp = fmaf(e1, e1, dp);
        float e2 = a - c + EPS; dn = fmaf(e2, e2, dn);
        float wa = linW[j], wb = linW[HO + j];
        y1 = fmaf(a, wa, fmaf(b, wb, y1));
        y2 = fmaf(a, wa, fmaf(c, wb, y2));
    }
    dp = sqrtf(dp); dn = sqrtf(dn);
    float sp = 1.0f / (1.0f + expf(-y1));
    float sn = 1.0f / (1.0f + expf(-y2));

    const int base = 3 * GG * HO;
    out[base + 1 + g] = sp;
    out[base + 1 + GG + g] = sn;
    if (dn - dp > 0.f) atomicAdd(&s1, 1);
    if (sp - sn > 0.f) atomicAdd(&s2, 1);
    __syncthreads();
    if (g == 0) {
        out[base] = (float)s1;
        out[base + 1 + 2 * GG] = (float)s2;
    }
}

// ---------------- host orchestration ------------------------------------------
extern "C" void kernel_launch(void* const* d_in, const int* in_sizes, int n_in,
                              void* d_out, int out_size)
{
    const float* x[3]     = { (const float*)d_in[0], (const float*)d_in[1], (const float*)d_in[2] };
    const int*   ei[3]    = { (const int*)d_in[3], (const int*)d_in[4], (const int*)d_in[5] };
    const int*   batch[3] = { (const int*)d_in[6], (const int*)d_in[7], (const int*)d_in[8] };
    const float* W0 = (const float*)d_in[9];
    const float* b0 = (const float*)d_in[10];
    const float* W1 = (const float*)d_in[11];
    const float* b1 = (const float*)d_in[12];
    const float* W2 = (const float*)d_in[13];
    const float* b2 = (const float*)d_in[14];
    const float* lin0W = (const float*)d_in[15];
    const float* lin0b = (const float*)d_in[16];
    const float* linW  = (const float*)d_in[17];
    const float* linb  = (const float*)d_in[18];
    float* out = (float*)d_out;

    static cudaStream_t st[3];
    static cudaEvent_t evRoot, evDone[3];
    static bool inited = false;
    if (!inited) {
        for (int i = 0; i < 3; i++) cudaStreamCreateWithFlags(&st[i], cudaStreamNonBlocking);
        cudaEventCreateWithFlags(&evRoot, cudaEventDisableTiming);
        for (int i = 0; i < 3; i++) cudaEventCreateWithFlags(&evDone[i], cudaEventDisableTiming);
        inited = true;
    }

    __half *aptr[3], *aggptr[3], *xhptr[3], *wtbase;
    {
        __half* hb;
        cudaGetSymbolAddress((void**)&hb, g_a);
        for (int i = 0; i < 3; i++) aptr[i] = hb + (size_t)i * NH;
        cudaGetSymbolAddress((void**)&hb, g_agg);
        for (int i = 0; i < 3; i++) aggptr[i] = hb + (size_t)i * NH;
        cudaGetSymbolAddress((void**)&hb, g_xh);
        for (int i = 0; i < 3; i++) xhptr[i] = hb + (size_t)i * NN * FIN;
        cudaGetSymbolAddress((void**)&wtbase, g_wt);
    }
    __half* wt1 = wtbase;                 // [256][256]
    __half* wt0 = wtbase + 256 * HH;      // [256][128]

    dim3 gemmGrid((NN + 127) / 128, HH / 128);
    int  warpBlocks = (int)(((long long)NN * 32 + 255) / 256);
    const int NB = (NN + 1023) / 1024;
    int  xcvtBlocks = (int)(((size_t)NN * FIN / 4 + 255) / 256);

    // weight transposes (shared by all passes) on the capture stream
    wt_kernel<<<(256 * HH + 255) / 256, 256>>>(W1, wt1, HH);
    wt_kernel<<<(256 * FIN + 255) / 256, 256>>>(W0, wt0, FIN);

    cudaEventRecord(evRoot, 0);

    for (int p = 0; p < 3; p++) {
        cudaStream_t s = st[p];
        cudaStreamWaitEvent(s, evRoot, 0);

        const int* srcp = ei[p];
        const int* dstp = ei[p] + EE;

        // ---- per-pass graph prep + x conversion ----
        zero_kernel<<<(NN + 255) / 256, 256, 0, s>>>(p);
        xcvt_kernel<<<xcvtBlocks, 256, 0, s>>>(x[p], xhptr[p]);
        deg_kernel<<<(EE + 255) / 256, 256, 0, s>>>(dstp, p);
        dinv_kernel<<<(NN + 255) / 256, 256, 0, s>>>(p);
        scan1_kernel<<<NB, 1024, 0, s>>>(p);
        scan2_kernel<<<1, 128, 0, s>>>(p);
        scan3_kernel<<<(NN + 255) / 256, 256, 0, s>>>(p);
        csr_kernel<<<(EE + 255) / 256, 256, 0, s>>>(srcp, dstp, p);
        pcnt_kernel<<<(NN + 255) / 256, 256, 0, s>>>(batch[p], p);

        // ---- layer 0: agg0 = Â x ; a = agg0 @ W0 + b0
        pullx_kernel<<<warpBlocks, 256, 0, s>>>(xhptr[p], aggptr[p], p);
        gemmh_kernel<FIN><<<gemmGrid, 256, 0, s>>>(aggptr[p], wt0, b0, aptr[p]);

        // ---- layer 1: agg1 = Â relu(a) ; a = agg1 @ W1 + b1
        pull_kernel<<<warpBlocks, 256, 0, s>>>(aptr[p], aggptr[p], nullptr, 0, p);
        gemmh_kernel<HH><<<gemmGrid, 256, 0, s>>>(aggptr[p], wt1, b1, aptr[p]);

        // ---- layer 2: psum = pool(Â relu(a))  (GEMM deferred to z_kernel)
        pull_kernel<<<warpBlocks, 256, 0, s>>>(aptr[p], nullptr, batch[p], 1, p);

        // ---- z = (psum/cnt @ W2 + b2) @ lin0W + lin0b
        z_kernel<<<GG, 256, 0, s>>>(W2, b2, lin0W, lin0b, out + (size_t)p * GG * HO, p);

        cudaEventRecord(evDone[p], s);
    }

    for (int p = 0; p < 3; p++) cudaStreamWaitEvent(0, evDone[p], 0);

    final_kernel<<<1, GG>>>(linW, linb, out);
}

// round 13
// speedup vs baseline: 2.0227x; 1.1452x over previous
#include <cuda_runtime.h>
#include <cuda_bf16.h>
#include <cuda_fp16.h>
#include <stdint.h>
#include <math.h>

// Problem constants (fixed by the dataset)
#define NN 100000
#define EE 3200000
#define FIN 128
#define HH  256
#define GG  64
#define HO  128   // H/2

typedef unsigned long long u64;

// ---------------- per-pass scratch (static device globals) --------------------
#define NH ((size_t)NN * HH)
__device__ __align__(16) __half g_a  [3][NH];                 // GEMM out (gather source)
__device__ __align__(16) __half g_agg[3][NH];                 // pull out (GEMM A input)
__device__ __align__(16) __half g_xh [3][(size_t)NN * FIN];   // fp16 x
__device__ __align__(16) __half g_wt [256 * HH + 256 * FIN];  // fp16 WT: W1 [256][256], W0 [256][128]
__device__ float g_dinv [3][NN];
__device__ float g_dinv2[3][NN];
__device__ int   g_deg  [3][NN];
__device__ __align__(16) float g_psum[3][GG * HH];
__device__ int   g_pcnt[3][GG];
__device__ int   g_rowptr[3][NN + 1];
__device__ int   g_off[3][NN];
__device__ int   g_bsum[3][128];
__device__ int   g_bsum2[3][128];
__device__ __align__(16) int2 g_epack[3][EE];   // (src, coef-as-int)

// ---------------- helpers ----------------------------------------------------
__device__ __forceinline__ void red_add_v4(float4* addr, float4 v) {
    asm volatile("red.global.add.v4.f32 [%0], {%1,%2,%3,%4};"
                 :: "l"(addr), "f"(v.x), "f"(v.y), "f"(v.z), "f"(v.w)
                 : "memory");
}
__device__ __forceinline__ uint32_t hrelu2(uint32_t v) {
    __half2 h = *reinterpret_cast<__half2*>(&v);
    __half2 z = __float2half2_rn(0.f);
    h = __hmax2(h, z);
    return *reinterpret_cast<uint32_t*>(&h);
}
__device__ __forceinline__ void hacc2r(float4& a, float cf, uint2 v, bool relu) {
    if (relu) { v.x = hrelu2(v.x); v.y = hrelu2(v.y); }
    float2 x0 = __half22float2(*reinterpret_cast<const __half2*>(&v.x));
    float2 x1 = __half22float2(*reinterpret_cast<const __half2*>(&v.y));
    a.x = fmaf(cf, x0.x, a.x); a.y = fmaf(cf, x0.y, a.y);
    a.z = fmaf(cf, x1.x, a.z); a.w = fmaf(cf, x1.y, a.w);
}
__device__ __forceinline__ uint2 pack_half4(float4 v) {
    __half2 h0 = __float22half2_rn(make_float2(v.x, v.y));
    __half2 h1 = __float22half2_rn(make_float2(v.z, v.w));
    uint2 s;
    s.x = *reinterpret_cast<uint32_t*>(&h0);
    s.y = *reinterpret_cast<uint32_t*>(&h1);
    return s;
}
__device__ __forceinline__ float4 unpack_half4(uint2 s) {
    float2 a = __half22float2(*reinterpret_cast<const __half2*>(&s.x));
    float2 b = __half22float2(*reinterpret_cast<const __half2*>(&s.y));
    return make_float4(a.x, a.y, b.x, b.y);
}
__device__ __forceinline__ void mma16816(float* c, const uint32_t* a, const uint32_t* b) {
    asm volatile(
        "mma.sync.aligned.m16n8k16.row.col.f32.f16.f16.f32 "
        "{%0,%1,%2,%3}, {%4,%5,%6,%7}, {%8,%9}, {%0,%1,%2,%3};"
        : "+f"(c[0]), "+f"(c[1]), "+f"(c[2]), "+f"(c[3])
        : "r"(a[0]), "r"(a[1]), "r"(a[2]), "r"(a[3]), "r"(b[0]), "r"(b[1]));
}

// ---------------- per-pass setup ---------------------------------------------
__global__ void zero_kernel(int p) {
    int i = blockIdx.x * blockDim.x + threadIdx.x;
    if (i < NN)      { g_deg[p][i] = 0; g_off[p][i] = 0; }
    if (i < GG * HH) g_psum[p][i] = 0.f;
    if (i < GG)      g_pcnt[p][i] = 0;
}

__global__ void deg_kernel(const int* __restrict__ dst, int p) {
    int e = blockIdx.x * blockDim.x + threadIdx.x;
    if (e < EE) atomicAdd(&g_deg[p][dst[e]], 1);
}

__global__ void dinv_kernel(int p) {
    int i = blockIdx.x * blockDim.x + threadIdx.x;
    if (i < NN) {
        float d = (float)g_deg[p][i] + 1.0f;
        g_dinv[p][i]  = rsqrtf(d);
        g_dinv2[p][i] = 1.0f / d;
    }
}

// x fp32 -> fp16
__global__ void xcvt_kernel(const float* __restrict__ x, __half* __restrict__ xh) {
    size_t i = ((size_t)blockIdx.x * blockDim.x + threadIdx.x) * 4;
    if (i >= (size_t)NN * FIN) return;
    float4 v = *reinterpret_cast<const float4*>(x + i);
    *reinterpret_cast<uint2*>(xh + i) = pack_half4(v);
}

// W [K][256] fp32 -> WT [256][K] fp16
__global__ void wt_kernel(const float* __restrict__ W, __half* __restrict__ WT, int K) {
    int idx = blockIdx.x * blockDim.x + threadIdx.x;
    if (idx >= 256 * K) return;
    int n = idx / K, k = idx % K;
    WT[idx] = __float2half(W[(size_t)k * 256 + n]);
}

// ---------------- exclusive scan of deg -> rowptr ------------------------------
__global__ void scan1_kernel(int p) {
    __shared__ int s[1024];
    int t = threadIdx.x;
    int i = blockIdx.x * 1024 + t;
    int v = (i < NN) ? g_deg[p][i] : 0;
    int x = v;
    s[t] = x;
    __syncthreads();
#pragma unroll
    for (int off = 1; off < 1024; off <<= 1) {
        int y = (t >= off) ? s[t - off] : 0;
        __syncthreads();
        x += y;
        s[t] = x;
        __syncthreads();
    }
    if (i < NN) g_rowptr[p][i] = x - v;
    if (t == 1023) g_bsum[p][blockIdx.x] = x;
}

__global__ void scan2_kernel(int p) {
    __shared__ int s[128];
    int t = threadIdx.x;
    const int NB = (NN + 1023) >> 10;
    int v = (t < NB) ? g_bsum[p][t] : 0;
    int x = v;
    s[t] = x;
    __syncthreads();
#pragma unroll
    for (int off = 1; off < 128; off <<= 1) {
        int y = (t >= off) ? s[t - off] : 0;
        __syncthreads();
        x += y;
        s[t] = x;
        __syncthreads();
    }
    g_bsum2[p][t] = x - v;
}

__global__ void scan3_kernel(int p) {
    int i = blockIdx.x * blockDim.x + threadIdx.x;
    if (i < NN) g_rowptr[p][i] += g_bsum2[p][i >> 10];
    if (i == 0) g_rowptr[p][NN] = EE;
}

__global__ void csr_kernel(const int* __restrict__ src, const int* __restrict__ dst, int p) {
    int e = blockIdx.x * blockDim.x + threadIdx.x;
    if (e >= EE) return;
    int s = src[e], d = dst[e];
    float coef = g_dinv[p][s] * g_dinv[p][d];
    int pos = g_rowptr[p][d] + atomicAdd(&g_off[p][d], 1);
    g_epack[p][pos] = make_int2(s, __float_as_int(coef));
}

__global__ void pcnt_kernel(const int* __restrict__ batch, int p) {
    int i = blockIdx.x * blockDim.x + threadIdx.x;
    if (i < NN) atomicAdd(&g_pcnt[p][batch[i]], 1);
}

// ---------------- layer-0 input aggregation: agg = Â x (fp16 in/out, MLP=8) ----
__global__ void __launch_bounds__(256)
pullx_kernel(const __half* __restrict__ xh, __half* __restrict__ agg, int p)
{
    int n = (int)((blockIdx.x * (unsigned)blockDim.x + threadIdx.x) >> 5);
    int lane = threadIdx.x & 31;
    if (n >= NN) return;
    int c = lane * 4;

    float d2 = g_dinv2[p][n];
    float4 sv = unpack_half4(*reinterpret_cast<const uint2*>(xh + (size_t)n * FIN + c));
    float4 acc = make_float4(sv.x * d2, sv.y * d2, sv.z * d2, sv.w * d2);

    int e = g_rowptr[p][n];
    int end = g_rowptr[p][n + 1];
    const int2* ep = g_epack[p];

    for (; e + 7 < end; e += 8) {
        int2 pe[8];
        uint2 v[8];
#pragma unroll
        for (int j = 0; j < 8; j++) pe[j] = ep[e + j];
#pragma unroll
        for (int j = 0; j < 8; j++)
            v[j] = *reinterpret_cast<const uint2*>(xh + (size_t)pe[j].x * FIN + c);
#pragma unroll
        for (int j = 0; j < 8; j++)
            hacc2r(acc, __int_as_float(pe[j].y), v[j], false);
    }
    for (; e < end; e++) {
        int2 pe = ep[e];
        uint2 v = *reinterpret_cast<const uint2*>(xh + (size_t)pe.x * FIN + c);
        hacc2r(acc, __int_as_float(pe.y), v, false);
    }

    *reinterpret_cast<uint2*>(agg + (size_t)n * FIN + c) = pack_half4(acc);
}

// ---------------- GEMM via HMMA: out = A @ W + bias (A fp16, out fp16) --------
template <int K>
__global__ void __launch_bounds__(256, 2)
gemmh_kernel(const __half* __restrict__ A, const __half* __restrict__ WT,
             const float* __restrict__ bias, __half* __restrict__ Hout)
{
    __shared__ uint32_t As2[16 * 136];
    __shared__ uint32_t Bs2[16 * 136];

    const int t = threadIdx.x;
    const int lane = t & 31;
    const int wid = t >> 5;
    const int g = lane >> 2;
    const int q = lane & 3;
    const int wm = wid & 3;
    const int wn = wid >> 2;
    const int rowBase = blockIdx.x * 128;
    const int colBase = blockIdx.y * 128;

    const int sr = t >> 1;
    const int sh = t & 1;

    float acc[2][8][4];
#pragma unroll
    for (int mt = 0; mt < 2; mt++)
#pragma unroll
        for (int nt = 0; nt < 8; nt++)
#pragma unroll
            for (int i = 0; i < 4; i++) acc[mt][nt][i] = 0.f;

    const int arow = rowBase + sr;
    uint4 pa0, pa1, pb0, pb1;
    {
        pa0 = make_uint4(0u,0u,0u,0u); pa1 = pa0;
        if (arow < NN) {
            const __half* ap = A + (size_t)arow * K + sh * 16;
            pa0 = *reinterpret_cast<const uint4*>(ap);
            pa1 = *reinterpret_cast<const uint4*>(ap + 8);
        }
        const __half* bp = WT + (size_t)(colBase + sr) * K + sh * 16;
        pb0 = *reinterpret_cast<const uint4*>(bp);
        pb1 = *reinterpret_cast<const uint4*>(bp + 8);
    }

    for (int kb = 0; kb < K; kb += 32) {
        {
            uint32_t av[8] = {pa0.x, pa0.y, pa0.z, pa0.w, pa1.x, pa1.y, pa1.z, pa1.w};
            uint32_t bv[8] = {pb0.x, pb0.y, pb0.z, pb0.w, pb1.x, pb1.y, pb1.z, pb1.w};
            int kp0 = sh * 8;
#pragma unroll
            for (int j = 0; j < 8; j++) {
                As2[(kp0 + j) * 136 + sr] = av[j];
                Bs2[(kp0 + j) * 136 + sr] = bv[j];
            }
        }
        __syncthreads();

        if (kb + 32 < K) {
            int kn = kb + 32;
            pa0 = make_uint4(0u,0u,0u,0u); pa1 = pa0;
            if (arow < NN) {
                const __half* ap = A + (size_t)arow * K + kn + sh * 16;
                pa0 = *reinterpret_cast<const uint4*>(ap);
                pa1 = *reinterpret_cast<const uint4*>(ap + 8);
            }
            const __half* bp = WT + (size_t)(colBase + sr) * K + kn + sh * 16;
            pb0 = *reinterpret_cast<const uint4*>(bp);
            pb1 = *reinterpret_cast<const uint4*>(bp + 8);
        }

#pragma unroll
        for (int s = 0; s < 2; s++) {
            int kp = s * 8 + q;
            uint32_t afr[2][4];
#pragma unroll
            for (int mt = 0; mt < 2; mt++) {
                int R = wm * 32 + mt * 16;
                afr[mt][0] = As2[kp * 136 + R + g];
                afr[mt][1] = As2[kp * 136 + R + 8 + g];
                afr[mt][2] = As2[(kp + 4) * 136 + R + g];
                afr[mt][3] = As2[(kp + 4) * 136 + R + 8 + g];
            }
            uint32_t bfr[8][2];
#pragma unroll
            for (int nt = 0; nt < 8; nt++) {
                int nc = wn * 64 + nt * 8 + g;
                bfr[nt][0] = Bs2[kp * 136 + nc];
                bfr[nt][1] = Bs2[(kp + 4) * 136 + nc];
            }
#pragma unroll
            for (int mt = 0; mt < 2; mt++)
#pragma unroll
                for (int nt = 0; nt < 8; nt++)
                    mma16816(acc[mt][nt], afr[mt], bfr[nt]);
        }
        __syncthreads();
    }

#pragma unroll
    for (int mt = 0; mt < 2; mt++) {
        int row0 = rowBase + wm * 32 + mt * 16 + g;
        int row1 = row0 + 8;
#pragma unroll
        for (int nt = 0; nt < 8; nt++) {
            int col = colBase + wn * 64 + nt * 8 + q * 2;
            float2 bb = *reinterpret_cast<const float2*>(bias + col);
            if (row0 < NN) {
                __half2 h = __float22half2_rn(make_float2(acc[mt][nt][0] + bb.x,
                                                          acc[mt][nt][1] + bb.y));
                *reinterpret_cast<uint32_t*>(Hout + (size_t)row0 * HH + col) =
                    *reinterpret_cast<uint32_t*>(&h);
            }
            if (row1 < NN) {
                __half2 h = __float22half2_rn(make_float2(acc[mt][nt][2] + bb.x,
                                                          acc[mt][nt][3] + bb.y));
                *reinterpret_cast<uint32_t*>(Hout + (size_t)row1 * HH + col) =
                    *reinterpret_cast<uint32_t*>(&h);
            }
        }
    }
}

// ---------------- pull (column-half): agg = Â relu(a), 128 cols per launch -----
// blockIdx.y selects the column half; per-phase gather working set 25.6 MB/pass.
// doPool==1: pooled directly into psum (no node-output store).
__global__ void __launch_bounds__(256)
pull_kernel(const __half* __restrict__ a, __half* __restrict__ agg,
            const int* __restrict__ batch, int doPool, int p)
{
    int n = (int)((blockIdx.x * (unsigned)blockDim.x + threadIdx.x) >> 5);
    int lane = threadIdx.x & 31;
    if (n >= NN) return;
    int c = blockIdx.y * 128 + lane * 4;

    float d2 = g_dinv2[p][n];
    float4 acc = make_float4(0.f, 0.f, 0.f, 0.f);
    {
        uint2 sv = *reinterpret_cast<const uint2*>(a + (size_t)n * HH + c);
        hacc2r(acc, d2, sv, true);
    }

    int e = g_rowptr[p][n];
    int end = g_rowptr[p][n + 1];
    const int2* ep = g_epack[p];

    for (; e + 7 < end; e += 8) {
        int2 pe[8];
        uint2 v[8];
#pragma unroll
        for (int j = 0; j < 8; j++) pe[j] = ep[e + j];
#pragma unroll
        for (int j = 0; j < 8; j++)
            v[j] = *reinterpret_cast<const uint2*>(a + (size_t)pe[j].x * HH + c);
#pragma unroll
        for (int j = 0; j < 8; j++)
            hacc2r(acc, __int_as_float(pe[j].y), v[j], true);
    }
    for (; e < end; e++) {
        int2 pe = ep[e];
        uint2 v = *reinterpret_cast<const uint2*>(a + (size_t)pe.x * HH + c);
        hacc2r(acc, __int_as_float(pe.y), v, true);
    }

    if (!doPool) {
        *reinterpret_cast<uint2*>(agg + (size_t)n * HH + c) = pack_half4(acc);
    } else {
        int g = __ldg(&batch[n]);
        red_add_v4(reinterpret_cast<float4*>(g_psum[p] + g * HH + c), acc);
    }
}

// ---------------- z: mean = psum/cnt ; t2 = mean@W2 + b2 ; z = t2@lin0W + lin0b -
__global__ void __launch_bounds__(256)
z_kernel(const float* __restrict__ W2, const float* __restrict__ b2,
         const float* __restrict__ lin0W, const float* __restrict__ lin0b,
         float* __restrict__ outz, int p)
{
    __shared__ float mean[HH];
    __shared__ float t2[HH];
    int g = blockIdx.x;
    int t = threadIdx.x;   // 0..255
    float cnt = fmaxf((float)g_pcnt[p][g], 1.0f);
    mean[t] = g_psum[p][g * HH + t] / cnt;
    __syncthreads();

    float acc = b2[t];
#pragma unroll 8
    for (int k = 0; k < HH; k++)
        acc = fmaf(mean[k], __ldg(&W2[(size_t)k * HH + t]), acc);
    t2[t] = acc;
    __syncthreads();

    if (t < HO) {
        float z = lin0b[t];
#pragma unroll 8
        for (int k = 0; k < HH; k++)
            z = fmaf(t2[k], __ldg(&lin0W[(size_t)k * HO + t]), z);
        outz[g * HO + t] = z;
    }
}

// ---------------- triplet head ------------------------------------------------
__global__ void final_kernel(const float* __restrict__ linW,
                             const float* __restrict__ linb,
                             float* __restrict__ out)
{
    __shared__ int s1, s2;
    int g = threadIdx.x;
    if (g == 0) { s1 = 0; s2 = 0; }
    __syncthreads();

    const float* z0 = out;
    const float* z1 = out + GG * HO;
    const float* z2 = out + 2 * GG * HO;
    const float EPS = 1e-6f;

    float dp = 0.f, dn = 0.f;
    float y1 = linb[0], y2 = linb[0];
#pragma unroll 4
    for (int j = 0; j < HO; j++) {
        float a = z0[g * HO + j];
        float b = z1[g * HO + j];
        float c = z2[g * HO + j];
        float e1 = a - b + EPS; dp = fmaf(e1, e1, dp);
        float e2 = a - c + EPS; dn = fmaf(e2, e2, dn);
        float wa = linW[j], wb = linW[HO + j];
        y1 = fmaf(a, wa, fmaf(b, wb, y1));
        y2 = fmaf(a, wa, fmaf(c, wb, y2));
    }
    dp = sqrtf(dp); dn = sqrtf(dn);
    float sp = 1.0f / (1.0f + expf(-y1));
    float sn = 1.0f / (1.0f + expf(-y2));

    const int base = 3 * GG * HO;
    out[base + 1 + g] = sp;
    out[base + 1 + GG + g] = sn;
    if (dn - dp > 0.f) atomicAdd(&s1, 1);
    if (sp - sn > 0.f) atomicAdd(&s2, 1);
    __syncthreads();
    if (g == 0) {
        out[base] = (float)s1;
        out[base + 1 + 2 * GG] = (float)s2;
    }
}

// ---------------- host orchestration ------------------------------------------
extern "C" void kernel_launch(void* const* d_in, const int* in_sizes, int n_in,
                              void* d_out, int out_size)
{
    const float* x[3]     = { (const float*)d_in[0], (const float*)d_in[1], (const float*)d_in[2] };
    const int*   ei[3]    = { (const int*)d_in[3], (const int*)d_in[4], (const int*)d_in[5] };
    const int*   batch[3] = { (const int*)d_in[6], (const int*)d_in[7], (const int*)d_in[8] };
    const float* W0 = (const float*)d_in[9];
    const float* b0 = (const float*)d_in[10];
    const float* W1 = (const float*)d_in[11];
    const float* b1 = (const float*)d_in[12];
    const float* W2 = (const float*)d_in[13];
    const float* b2 = (const float*)d_in[14];
    const float* lin0W = (const float*)d_in[15];
    const float* lin0b = (const float*)d_in[16];
    const float* linW  = (const float*)d_in[17];
    const float* linb  = (const float*)d_in[18];
    float* out = (float*)d_out;

    static cudaStream_t st[3];
    static cudaEvent_t evRoot, evDone[3];
    static bool inited = false;
    if (!inited) {
        for (int i = 0; i < 3; i++) cudaStreamCreateWithFlags(&st[i], cudaStreamNonBlocking);
        cudaEventCreateWithFlags(&evRoot, cudaEventDisableTiming);
        for (int i = 0; i < 3; i++) cudaEventCreateWithFlags(&evDone[i], cudaEventDisableTiming);
        inited = true;
    }

    __half *aptr[3], *aggptr[3], *xhptr[3], *wtbase;
    {
        __half* hb;
        cudaGetSymbolAddress((void**)&hb, g_a);
        for (int i = 0; i < 3; i++) aptr[i] = hb + (size_t)i * NH;
        cudaGetSymbolAddress((void**)&hb, g_agg);
        for (int i = 0; i < 3; i++) aggptr[i] = hb + (size_t)i * NH;
        cudaGetSymbolAddress((void**)&hb, g_xh);
        for (int i = 0; i < 3; i++) xhptr[i] = hb + (size_t)i * NN * FIN;
        cudaGetSymbolAddress((void**)&wtbase, g_wt);
    }
    __half* wt1 = wtbase;                 // [256][256]
    __half* wt0 = wtbase + 256 * HH;      // [256][128]

    dim3 gemmGrid((NN + 127) / 128, HH / 128);
    int  warpBlocks = (int)(((long long)NN * 32 + 255) / 256);
    dim3 pullGrid(warpBlocks, 2);
    const int NB = (NN + 1023) / 1024;
    int  xcvtBlocks = (int)(((size_t)NN * FIN / 4 + 255) / 256);

    // weight transposes (shared by all passes) on the capture stream
    wt_kernel<<<(256 * HH + 255) / 256, 256>>>(W1, wt1, HH);
    wt_kernel<<<(256 * FIN + 255) / 256, 256>>>(W0, wt0, FIN);

    cudaEventRecord(evRoot, 0);

    for (int p = 0; p < 3; p++) {
        cudaStream_t s = st[p];
        cudaStreamWaitEvent(s, evRoot, 0);

        const int* srcp = ei[p];
        const int* dstp = ei[p] + EE;

        // ---- per-pass graph prep + x conversion ----
        zero_kernel<<<(NN + 255) / 256, 256, 0, s>>>(p);
        xcvt_kernel<<<xcvtBlocks, 256, 0, s>>>(x[p], xhptr[p]);
        deg_kernel<<<(EE + 255) / 256, 256, 0, s>>>(dstp, p);
        dinv_kernel<<<(NN + 255) / 256, 256, 0, s>>>(p);
        scan1_kernel<<<NB, 1024, 0, s>>>(p);
        scan2_kernel<<<1, 128, 0, s>>>(p);
        scan3_kernel<<<(NN + 255) / 256, 256, 0, s>>>(p);
        csr_kernel<<<(EE + 255) / 256, 256, 0, s>>>(srcp, dstp, p);
        pcnt_kernel<<<(NN + 255) / 256, 256, 0, s>>>(batch[p], p);

        // ---- layer 0: agg0 = Â x ; a = agg0 @ W0 + b0
        pullx_kernel<<<warpBlocks, 256, 0, s>>>(xhptr[p], aggptr[p], p);
        gemmh_kernel<FIN><<<gemmGrid, 256, 0, s>>>(aggptr[p], wt0, b0, aptr[p]);

        // ---- layer 1: agg1 = Â relu(a) (2 column halves) ; a = agg1 @ W1 + b1
        pull_kernel<<<pullGrid, 256, 0, s>>>(aptr[p], aggptr[p], nullptr, 0, p);
        gemmh_kernel<HH><<<gemmGrid, 256, 0, s>>>(aggptr[p], wt1, b1, aptr[p]);

        // ---- layer 2: psum = pool(Â relu(a))  (2 column halves)
        pull_kernel<<<pullGrid, 256, 0, s>>>(aptr[p], nullptr, batch[p], 1, p);

        // ---- z = (psum/cnt @ W2 + b2) @ lin0W + lin0b
        z_kernel<<<GG, 256, 0, s>>>(W2, b2, lin0W, lin0b, out + (size_t)p * GG * HO, p);

        cudaEventRecord(evDone[p], s);
    }

    for (int p = 0; p < 3; p++) cudaStreamWaitEvent(0, evDone[p], 0);

    final_kernel<<<1, GG>>>(linW, linb, out);
}